// round 7
// baseline (speedup 1.0000x reference)
#include <cuda_runtime.h>
#include <cuda_fp16.h>
#include <math.h>

#define NN 100000
#define EE 1600000
#define EPSV 1e-16f
#define NEG_SLOPE 0.2f
#define FULL 0xffffffffu
#define G1B 1563          // gemm1 blocks; each also handles a 1024-edge hist slice

// ---------------- scratch (device globals; allocation-free) ----------------
__device__ __half2 g_h1h[NN * 64];     // h1 [N,128] fp16       25.6 MB
__device__ float   g_as1[NN * 8];      // alpha_src1 [N,8]       3.2 MB
__device__ float   g_ad1[NN * 8];      // alpha_dst1 [N,8]       3.2 MB
__device__ float4  g_out1[NN * 32];    // elu(out1) [N,128]     51.2 MB
__device__ float4  g_g2[NN * 10];      // g2 [N,40]               16 MB
__device__ float   g_as2[NN];          // alpha_src2 [N]
__device__ float   g_ad2[NN];          // alpha_dst2 [N]
// CSR sort scratch (self-cleaning across runs)
__device__ int     g_deg[NN];          // zero-init .bss; drained by scatter
__device__ int     g_off[NN + 1];
__device__ int     g_ssrc[EE];         // src sorted by dst      6.4 MB
__device__ int          g_psum[98];
__device__ volatile int g_flag[98];    // zero-init; reader resets

// ---------------- helpers ----------------
__device__ __forceinline__ void fma4(float4& a, float s, float4 b) {
    a.x += s * b.x; a.y += s * b.y; a.z += s * b.z; a.w += s * b.w;
}
__device__ __forceinline__ float dot4(float4 a, float4 b) {
    return a.x * b.x + a.y * b.y + a.z * b.z + a.w * b.w;
}
__device__ __forceinline__ float leaky_exp(float e) {
    float t = e > 0.f ? e : NEG_SLOPE * e;
    return __expf(t);
}

// ---------------- 1. fusedA: gemm1 then per-block hist slice ---------------
// gemm1: 64 nodes x 128 cols register-tiled, whole W1 + x tile in 96KB smem.
// After the epilogue, each block histograms its ~1024-edge slice of dst:
// atomic latency hides under other blocks' FMA work.
__global__ __launch_bounds__(256) void fusedA_kernel(
    const float* __restrict__ x, const float* __restrict__ W1,
    const float* __restrict__ a_src, const float* __restrict__ a_dst,
    const int* __restrict__ dst)
{
    extern __shared__ float smem[];
    float4* sW4 = (float4*)smem;                 // [k*32 + c4]  64 KB
    float4* sx4 = (float4*)(smem + 128 * 128);   // [n*32 + k4]  32 KB
    const int tid = threadIdx.x;
    const int cx = tid & 31;      // col quad
    const int ny = tid >> 5;      // node group of 8
    const int nbase = blockIdx.x * 64;
    const float4* W4 = (const float4*)W1;
    const float4* x4 = (const float4*)x;

    #pragma unroll
    for (int it = 0; it < 16; it++)              // W: 4096 f4
        sW4[tid + it * 256] = W4[tid + it * 256];
    #pragma unroll
    for (int it = 0; it < 8; it++) {             // x: 2048 f4
        int f = tid + it * 256;
        int gn = nbase + (f >> 5);
        sx4[f] = (gn < NN) ? x4[(size_t)gn * 32 + (f & 31)]
                           : make_float4(0.f, 0.f, 0.f, 0.f);
    }
    __syncthreads();

    float4 c[8];
    #pragma unroll
    for (int i = 0; i < 8; i++) c[i] = make_float4(0.f, 0.f, 0.f, 0.f);

    #pragma unroll 4
    for (int k = 0; k < 128; k += 4) {
        float4 w0 = sW4[(k + 0) * 32 + cx];
        float4 w1 = sW4[(k + 1) * 32 + cx];
        float4 w2 = sW4[(k + 2) * 32 + cx];
        float4 w3 = sW4[(k + 3) * 32 + cx];
        #pragma unroll
        for (int i = 0; i < 8; i++) {
            float4 xv = sx4[(ny * 8 + i) * 32 + (k >> 2)];   // warp broadcast
            fma4(c[i], xv.x, w0); fma4(c[i], xv.y, w1);
            fma4(c[i], xv.z, w2); fma4(c[i], xv.w, w3);
        }
    }

    const int head = cx >> 2, cq = cx & 3;
    const float4 asv = ((const float4*)a_src)[head * 4 + cq];
    const float4 adv = ((const float4*)a_dst)[head * 4 + cq];
    #pragma unroll
    for (int i = 0; i < 8; i++) {
        int gn = nbase + ny * 8 + i;
        float ps = dot4(c[i], asv);
        float pd = dot4(c[i], adv);
        ps += __shfl_xor_sync(FULL, ps, 1); ps += __shfl_xor_sync(FULL, ps, 2);
        pd += __shfl_xor_sync(FULL, pd, 1); pd += __shfl_xor_sync(FULL, pd, 2);
        if (gn < NN) {
            __half2 p0 = __floats2half2_rn(c[i].x, c[i].y);
            __half2 p1 = __floats2half2_rn(c[i].z, c[i].w);
            uint2 pk = make_uint2(*(unsigned*)&p0, *(unsigned*)&p1);
            *(uint2*)&g_h1h[gn * 64 + 2 * cx] = pk;
            if (cq == 0) { g_as1[gn * 8 + head] = ps; g_ad1[gn * 8 + head] = pd; }
        }
    }

    // ---- histogram slice: edges [blockIdx*1024, +1024) ----
    const int ebase = blockIdx.x * 1024;
    #pragma unroll
    for (int it = 0; it < 4; it++) {
        int i = ebase + it * 256 + tid;
        if (i < EE) atomicAdd(&g_deg[__ldcs(dst + i)], 1);
    }
}

// ---------------- 2. domino scan: g_off = exclusive_scan(g_deg) -------------
// 98 blocks x 1024 threads, all resident (98 < 148 SMs) -> spin-safe.
__global__ __launch_bounds__(1024) void scan_kernel() {
    const int t = threadIdx.x;
    const int b = blockIdx.x;
    const int i = b * 1024 + t;
    int v = (i < NN) ? g_deg[i] : 0;
    int lane = t & 31, w = t >> 5;
    int xv = v;
    #pragma unroll
    for (int o = 1; o < 32; o <<= 1) {
        int y = __shfl_up_sync(FULL, xv, o);
        if (lane >= o) xv += y;
    }
    __shared__ int wt[32];
    __shared__ int blockpre;
    if (lane == 31) wt[w] = xv;
    __syncthreads();
    if (w == 0) {
        int z = wt[lane];
        #pragma unroll
        for (int o = 1; o < 32; o <<= 1) {
            int y = __shfl_up_sync(FULL, z, o);
            if (lane >= o) z += y;
        }
        wt[lane] = z;
    }
    __syncthreads();
    const int total = wt[31];
    if (t == 0) {                       // domino chain
        int pre = 0;
        if (b > 0) {
            while (g_flag[b - 1] == 0) { }
            __threadfence();
            pre = g_psum[b - 1];
            g_flag[b - 1] = 0;          // self-clean for next run
        }
        blockpre = pre;
        if (b < 97) {
            g_psum[b] = pre + total;
            __threadfence();
            g_flag[b] = 1;
        }
    }
    __syncthreads();
    int pre = blockpre + (w ? wt[w - 1] : 0);
    if (i < NN) g_off[i] = pre + xv - v;
    if (i == NN - 1) g_off[NN] = EE;
}

// ---------------- 3. scatter src into CSR order (drains g_deg to 0) ---------
__global__ __launch_bounds__(256) void scatter_kernel(
    const int* __restrict__ src, const int* __restrict__ dst)
{
    int i = blockIdx.x * 256 + threadIdx.x;
    int d = __ldcs(dst + i);
    int s = __ldcs(src + i);
    int p = g_off[d] + atomicSub(&g_deg[d], 1) - 1;
    __stcs(&g_ssrc[p], s);
}

// ---------------- 4. L1 fused aggregate: warp per node, one pass, fp16 h ----
__global__ __launch_bounds__(256) void agg1_kernel(const float* __restrict__ b1)
{
    const int n = (blockIdx.x * 256 + threadIdx.x) >> 5;   // node (grid exact)
    const int l = threadIdx.x & 31;
    const int beg = g_off[n], end = g_off[n + 1];
    const int head = l >> 2;
    const float adp = g_ad1[n * 8 + head];
    const uint2* h16 = (const uint2*)g_h1h;      // [n*32 + l] -> 4 halves

    float den = 0.f;
    float4 acc = make_float4(0.f, 0.f, 0.f, 0.f);

    for (int base = beg; base < end; base += 32) {
        const int je = min(32, end - base);
        const int sj = (l < je) ? __ldg(&g_ssrc[base + l]) : 0;
        int k = 0;
        #pragma unroll 1
        for (; k + 4 <= je; k += 4) {
            int s0 = __shfl_sync(FULL, sj, k);
            int s1 = __shfl_sync(FULL, sj, k + 1);
            int s2 = __shfl_sync(FULL, sj, k + 2);
            int s3 = __shfl_sync(FULL, sj, k + 3);
            float e0 = leaky_exp(__ldg(&g_as1[s0 * 8 + head]) + adp);
            float e1 = leaky_exp(__ldg(&g_as1[s1 * 8 + head]) + adp);
            float e2 = leaky_exp(__ldg(&g_as1[s2 * 8 + head]) + adp);
            float e3 = leaky_exp(__ldg(&g_as1[s3 * 8 + head]) + adp);
            uint2 p0 = __ldg(&h16[s0 * 32 + l]);
            uint2 p1 = __ldg(&h16[s1 * 32 + l]);
            uint2 p2 = __ldg(&h16[s2 * 32 + l]);
            uint2 p3 = __ldg(&h16[s3 * 32 + l]);
            den += (e0 + e1) + (e2 + e3);
            float2 a0 = __half22float2(*(__half2*)&p0.x), b0 = __half22float2(*(__half2*)&p0.y);
            float2 a1 = __half22float2(*(__half2*)&p1.x), b1v = __half22float2(*(__half2*)&p1.y);
            float2 a2 = __half22float2(*(__half2*)&p2.x), b2v = __half22float2(*(__half2*)&p2.y);
            float2 a3 = __half22float2(*(__half2*)&p3.x), b3 = __half22float2(*(__half2*)&p3.y);
            acc.x += e0 * a0.x + e1 * a1.x + e2 * a2.x + e3 * a3.x;
            acc.y += e0 * a0.y + e1 * a1.y + e2 * a2.y + e3 * a3.y;
            acc.z += e0 * b0.x + e1 * b1v.x + e2 * b2v.x + e3 * b3.x;
            acc.w += e0 * b0.y + e1 * b1v.y + e2 * b2v.y + e3 * b3.y;
        }
        for (; k < je; k++) {
            int s = __shfl_sync(FULL, sj, k);
            float e = leaky_exp(__ldg(&g_as1[s * 8 + head]) + adp);
            den += e;
            uint2 p = __ldg(&h16[s * 32 + l]);
            float2 a = __half22float2(*(__half2*)&p.x);
            float2 b = __half22float2(*(__half2*)&p.y);
            acc.x += e * a.x; acc.y += e * a.y;
            acc.z += e * b.x; acc.w += e * b.y;
        }
    }
    const float rinv = 1.f / (den + EPSV);
    float4 v = ((const float4*)b1)[l];
    v.x += acc.x * rinv; v.y += acc.y * rinv;
    v.z += acc.z * rinv; v.w += acc.w * rinv;
    v.x = v.x > 0.f ? v.x : __expf(v.x) - 1.f;
    v.y = v.y > 0.f ? v.y : __expf(v.y) - 1.f;
    v.z = v.z > 0.f ? v.z : __expf(v.z) - 1.f;
    v.w = v.w > 0.f ? v.w : __expf(v.w) - 1.f;
    g_out1[n * 32 + l] = v;
}

// ---------------- 5. GEMM2: g2 = elu_h @ W2 [128->40] + scalar alphas -------
__global__ __launch_bounds__(256) void gemm2_kernel(
    const float* __restrict__ W2, const float* __restrict__ a_src,
    const float* __restrict__ a_dst)
{
    __shared__ float4 sW[128 * 10];
    __shared__ float4 sas[10], sad[10];
    __shared__ float  sx[256 * 17];
    const int tid = threadIdx.x;
    const int node = blockIdx.x * 256 + tid;
    const float4* W4 = (const float4*)W2;
    #pragma unroll
    for (int it = 0; it < 5; it++) sW[tid + it * 256] = W4[tid + it * 256];
    if (tid < 10) { sas[tid] = ((const float4*)a_src)[tid];
                    sad[tid] = ((const float4*)a_dst)[tid]; }
    const float* hin = (const float*)g_out1;

    float4 acc[10];
    #pragma unroll
    for (int j = 0; j < 10; j++) acc[j] = make_float4(0, 0, 0, 0);

    for (int kc = 0; kc < 8; kc++) {
        __syncthreads();
        #pragma unroll
        for (int it = 0; it < 16; it++) {
            int f = tid + it * 256;
            int nl2 = f >> 4, k = f & 15;
            int gn = blockIdx.x * 256 + nl2;
            sx[nl2 * 17 + k] = (gn < NN) ? hin[(size_t)gn * 128 + kc * 16 + k] : 0.f;
        }
        __syncthreads();
        #pragma unroll
        for (int k = 0; k < 16; k++) {
            float xv = sx[tid * 17 + k];
            const float4* wr = &sW[(kc * 16 + k) * 10];
            #pragma unroll
            for (int j = 0; j < 10; j++) fma4(acc[j], xv, wr[j]);
        }
    }
    if (node < NN) {
        float s = 0.f, d = 0.f;
        #pragma unroll
        for (int j = 0; j < 10; j++) { s += dot4(acc[j], sas[j]); d += dot4(acc[j], sad[j]); }
        #pragma unroll
        for (int j = 0; j < 10; j++) g_g2[node * 10 + j] = acc[j];
        g_as2[node] = s;
        g_ad2[node] = d;
    }
}

// ---------------- 6. L2 fused aggregate (one pass) + bias + log_softmax -----
__global__ __launch_bounds__(256) void agg2_kernel(
    const float* __restrict__ b2, float* __restrict__ out)
{
    const int n = (blockIdx.x * 256 + threadIdx.x) >> 5;
    const int l = threadIdx.x & 31;
    const int beg = g_off[n], end = g_off[n + 1];
    const float ad2n = g_ad2[n];
    const bool act = l < 10;

    float den = 0.f;
    float4 acc = make_float4(0.f, 0.f, 0.f, 0.f);

    for (int base = beg; base < end; base += 32) {
        const int je = min(32, end - base);
        const int sj = (l < je) ? __ldg(&g_ssrc[base + l]) : 0;
        int k = 0;
        #pragma unroll 1
        for (; k + 4 <= je; k += 4) {
            int s0 = __shfl_sync(FULL, sj, k);
            int s1 = __shfl_sync(FULL, sj, k + 1);
            int s2 = __shfl_sync(FULL, sj, k + 2);
            int s3 = __shfl_sync(FULL, sj, k + 3);
            float e0 = leaky_exp(__ldg(&g_as2[s0]) + ad2n);
            float e1 = leaky_exp(__ldg(&g_as2[s1]) + ad2n);
            float e2 = leaky_exp(__ldg(&g_as2[s2]) + ad2n);
            float e3 = leaky_exp(__ldg(&g_as2[s3]) + ad2n);
            den += (e0 + e1) + (e2 + e3);
            if (act) {
                fma4(acc, e0, g_g2[s0 * 10 + l]);
                fma4(acc, e1, g_g2[s1 * 10 + l]);
                fma4(acc, e2, g_g2[s2 * 10 + l]);
                fma4(acc, e3, g_g2[s3 * 10 + l]);
            }
        }
        for (; k < je; k++) {
            int s = __shfl_sync(FULL, sj, k);
            float e = leaky_exp(__ldg(&g_as2[s]) + ad2n);
            den += e;
            if (act) fma4(acc, e, g_g2[s * 10 + l]);
        }
    }
    const float rinv = 1.f / (den + EPSV);

    float4 v = make_float4(-1e30f, -1e30f, -1e30f, -1e30f);
    if (act) {
        v = ((const float4*)b2)[l];
        v.x += acc.x * rinv; v.y += acc.y * rinv;
        v.z += acc.z * rinv; v.w += acc.w * rinv;
    }
    float mx = act ? fmaxf(fmaxf(v.x, v.y), fmaxf(v.z, v.w)) : -1e30f;
    #pragma unroll
    for (int o = 16; o; o >>= 1) mx = fmaxf(mx, __shfl_xor_sync(FULL, mx, o));
    float sm = 0.f;
    if (act) sm = __expf(v.x - mx) + __expf(v.y - mx) + __expf(v.z - mx) + __expf(v.w - mx);
    #pragma unroll
    for (int o = 16; o; o >>= 1) sm += __shfl_xor_sync(FULL, sm, o);
    float lse = mx + logf(sm);
    if (act)
        ((float4*)out)[n * 10 + l] =
            make_float4(v.x - lse, v.y - lse, v.z - lse, v.w - lse);
}

// ---------------- launch ----------------
extern "C" void kernel_launch(void* const* d_in, const int* in_sizes, int n_in,
                              void* d_out, int out_size)
{
    const float* x      = (const float*)d_in[0];
    const int*   eidx   = (const int*)d_in[1];
    const float* W1     = (const float*)d_in[2];
    const float* a_src1 = (const float*)d_in[3];
    const float* a_dst1 = (const float*)d_in[4];
    const float* b1     = (const float*)d_in[5];
    const float* W2     = (const float*)d_in[6];
    const float* a_src2 = (const float*)d_in[7];
    const float* a_dst2 = (const float*)d_in[8];
    const float* b2     = (const float*)d_in[9];
    const int* src = eidx;
    const int* dst = eidx + EE;
    float* out = (float*)d_out;

    const int G1_SMEM = (128 * 128 + 64 * 128) * 4;   // 96 KB
    (void)cudaFuncSetAttribute(fusedA_kernel,
                               cudaFuncAttributeMaxDynamicSharedMemorySize, G1_SMEM);

    fusedA_kernel<<<G1B, 256, G1_SMEM>>>(x, W1, a_src1, a_dst1, dst);      // 1
    scan_kernel<<<98, 1024>>>();                                           // 2
    scatter_kernel<<<EE / 256, 256>>>(src, dst);                           // 3
    agg1_kernel<<<NN / 8, 256>>>(b1);                                      // 4 (ncu)
    gemm2_kernel<<<(NN + 255) / 256, 256>>>(W2, a_src2, a_dst2);           // 5
    agg2_kernel<<<NN / 8, 256>>>(b2, out);                                 // 6
}

// round 8
// speedup vs baseline: 1.3605x; 1.3605x over previous
#include <cuda_runtime.h>
#include <cuda_fp16.h>
#include <math.h>

#define NN 100000
#define EE 1600000
#define EPSV 1e-16f
#define NEG_SLOPE 0.2f
#define FULL 0xffffffffu

// ---------------- scratch (device globals; allocation-free) ----------------
__device__ __half2 g_h1h[NN * 64];     // h1 [N,128] fp16       25.6 MB
__device__ float   g_as1[NN * 8];      // alpha_src1 [N,8]       3.2 MB
__device__ float   g_ad1[NN * 8];      // alpha_dst1 [N,8]       3.2 MB
__device__ float4  g_out1[NN * 32];    // elu(out1) [N,128]     51.2 MB
__device__ float4  g_g2[NN * 10];      // g2 [N,40]               16 MB
__device__ float   g_as2[NN];          // alpha_src2 [N]
__device__ float   g_ad2[NN];          // alpha_dst2 [N]
// CSR sort scratch
__device__ int     g_deg[NN];
__device__ int     g_off[NN + 1];
__device__ int     g_pos[NN];
__device__ int     g_ssrc[EE];         // src sorted by dst      6.4 MB
__device__ int     g_bsum[128];

// ---------------- helpers ----------------
__device__ __forceinline__ void fma4(float4& a, float s, float4 b) {
    a.x += s * b.x; a.y += s * b.y; a.z += s * b.z; a.w += s * b.w;
}
__device__ __forceinline__ float dot4(float4 a, float4 b) {
    return a.x * b.x + a.y * b.y + a.z * b.z + a.w * b.w;
}
__device__ __forceinline__ float leaky_exp(float e) {
    float t = e > 0.f ? e : NEG_SLOPE * e;
    return __expf(t);
}

// ---------------- 0. zero sort counters ----------------
__global__ __launch_bounds__(256) void zero_kernel() {
    int i = blockIdx.x * 256 + threadIdx.x;
    if (i < NN) { g_deg[i] = 0; g_pos[i] = 0; }
}

// ---------------- S1. histogram of dst ----------------
__global__ __launch_bounds__(256) void hist_kernel(const int* __restrict__ dst) {
    int i = blockIdx.x * 256 + threadIdx.x;
    atomicAdd(&g_deg[__ldcs(dst + i)], 1);
}

// ---------------- S2a. block-level exclusive scan of degrees ----------------
__global__ __launch_bounds__(1024) void scan1_kernel() {
    int t = threadIdx.x;
    int i = blockIdx.x * 1024 + t;
    int v = (i < NN) ? g_deg[i] : 0;
    int lane = t & 31, w = t >> 5;
    int x = v;
    #pragma unroll
    for (int o = 1; o < 32; o <<= 1) {
        int y = __shfl_up_sync(FULL, x, o);
        if (lane >= o) x += y;
    }
    __shared__ int wt[32];
    if (lane == 31) wt[w] = x;
    __syncthreads();
    if (w == 0) {
        int z = wt[lane];
        #pragma unroll
        for (int o = 1; o < 32; o <<= 1) {
            int y = __shfl_up_sync(FULL, z, o);
            if (lane >= o) z += y;
        }
        wt[lane] = z;
    }
    __syncthreads();
    int pre = (w ? wt[w - 1] : 0);
    if (i < NN) g_off[i] = pre + x - v;      // block-local exclusive
    if (t == 1023) g_bsum[blockIdx.x] = wt[31];
}

// ---------------- S2b. add block prefix (scan2+scan3 fused) ----------------
__global__ __launch_bounds__(1024) void scanB_kernel() {
    __shared__ int s[128];
    __shared__ int blockpre;
    int t = threadIdx.x;
    if (t < 128) s[t] = (t < 98) ? g_bsum[t] : 0;
    __syncthreads();
    if (t == 0) {
        int run = 0;
        for (int b = 0; b < blockIdx.x; b++) run += s[b];
        blockpre = run;
    }
    __syncthreads();
    int i = blockIdx.x * 1024 + t;
    if (i < NN) g_off[i] += blockpre;
    if (i == 0) g_off[NN] = EE;
}

// ---------------- S3. scatter src into CSR order ----------------
__global__ __launch_bounds__(256) void scatter_kernel(
    const int* __restrict__ src, const int* __restrict__ dst)
{
    int i = blockIdx.x * 256 + threadIdx.x;
    int d = __ldcs(dst + i);
    int s = __ldcs(src + i);
    int p = g_off[d] + atomicAdd(&g_pos[d], 1);
    __stcs(&g_ssrc[p], s);
}

// ---------------- 1. GEMM1 (register-tiled): h1(fp16) = x@W1 + alphas -------
// Block: 64 nodes x 128 cols, K=128 in one stage. 256 threads.
// Thread (cx = tid&31, ny = tid>>5): 8 nodes x 4 cols (32 accumulators).
// Dynamic smem: sW[128k x 128c] (64 KB) + sx[64n x 128k] (32 KB) = 96 KB.
__global__ __launch_bounds__(256) void gemm1_kernel(
    const float* __restrict__ x, const float* __restrict__ W1,
    const float* __restrict__ a_src, const float* __restrict__ a_dst)
{
    extern __shared__ float smem[];
    float4* sW4 = (float4*)smem;                 // [k*32 + c4]
    float4* sx4 = (float4*)(smem + 128 * 128);   // [n*32 + k4]
    const int tid = threadIdx.x;
    const int cx = tid & 31;      // col quad
    const int ny = tid >> 5;      // node group of 8
    const int nbase = blockIdx.x * 64;
    const float4* W4 = (const float4*)W1;
    const float4* x4 = (const float4*)x;

    #pragma unroll
    for (int it = 0; it < 16; it++)              // W: 4096 f4
        sW4[tid + it * 256] = W4[tid + it * 256];
    #pragma unroll
    for (int it = 0; it < 8; it++) {             // x: 2048 f4
        int f = tid + it * 256;
        int gn = nbase + (f >> 5);
        sx4[f] = (gn < NN) ? x4[(size_t)gn * 32 + (f & 31)]
                           : make_float4(0.f, 0.f, 0.f, 0.f);
    }
    __syncthreads();

    float4 c[8];
    #pragma unroll
    for (int i = 0; i < 8; i++) c[i] = make_float4(0.f, 0.f, 0.f, 0.f);

    #pragma unroll 4
    for (int k = 0; k < 128; k += 4) {
        float4 w0 = sW4[(k + 0) * 32 + cx];
        float4 w1 = sW4[(k + 1) * 32 + cx];
        float4 w2 = sW4[(k + 2) * 32 + cx];
        float4 w3 = sW4[(k + 3) * 32 + cx];
        #pragma unroll
        for (int i = 0; i < 8; i++) {
            float4 xv = sx4[(ny * 8 + i) * 32 + (k >> 2)];   // warp broadcast
            fma4(c[i], xv.x, w0); fma4(c[i], xv.y, w1);
            fma4(c[i], xv.z, w2); fma4(c[i], xv.w, w3);
        }
    }

    // epilogue: store h1 (fp16) + per-head alpha dots
    const int head = cx >> 2, cq = cx & 3;
    const float4 asv = ((const float4*)a_src)[head * 4 + cq];
    const float4 adv = ((const float4*)a_dst)[head * 4 + cq];
    #pragma unroll
    for (int i = 0; i < 8; i++) {
        int gn = nbase + ny * 8 + i;
        float ps = dot4(c[i], asv);
        float pd = dot4(c[i], adv);
        ps += __shfl_xor_sync(FULL, ps, 1); ps += __shfl_xor_sync(FULL, ps, 2);
        pd += __shfl_xor_sync(FULL, pd, 1); pd += __shfl_xor_sync(FULL, pd, 2);
        if (gn < NN) {
            __half2 p0 = __floats2half2_rn(c[i].x, c[i].y);
            __half2 p1 = __floats2half2_rn(c[i].z, c[i].w);
            uint2 pk = make_uint2(*(unsigned*)&p0, *(unsigned*)&p1);
            *(uint2*)&g_h1h[gn * 64 + 2 * cx] = pk;
            if (cq == 0) { g_as1[gn * 8 + head] = ps; g_ad1[gn * 8 + head] = pd; }
        }
    }
}

// ---------------- 2. L1 fused aggregate: warp per node, one pass, fp16 h ----
__global__ __launch_bounds__(256) void agg1_kernel(const float* __restrict__ b1)
{
    const int n = (blockIdx.x * 256 + threadIdx.x) >> 5;   // node (grid exact)
    const int l = threadIdx.x & 31;
    const int beg = g_off[n], end = g_off[n + 1];
    const int head = l >> 2;
    const float adp = g_ad1[n * 8 + head];
    const uint2* h16 = (const uint2*)g_h1h;      // [n*32 + l] -> 4 halves

    float den = 0.f;
    float4 acc = make_float4(0.f, 0.f, 0.f, 0.f);

    for (int base = beg; base < end; base += 32) {
        const int je = min(32, end - base);
        const int sj = (l < je) ? __ldg(&g_ssrc[base + l]) : 0;
        int k = 0;
        #pragma unroll 1
        for (; k + 4 <= je; k += 4) {
            int s0 = __shfl_sync(FULL, sj, k);
            int s1 = __shfl_sync(FULL, sj, k + 1);
            int s2 = __shfl_sync(FULL, sj, k + 2);
            int s3 = __shfl_sync(FULL, sj, k + 3);
            float e0 = leaky_exp(__ldg(&g_as1[s0 * 8 + head]) + adp);
            float e1 = leaky_exp(__ldg(&g_as1[s1 * 8 + head]) + adp);
            float e2 = leaky_exp(__ldg(&g_as1[s2 * 8 + head]) + adp);
            float e3 = leaky_exp(__ldg(&g_as1[s3 * 8 + head]) + adp);
            uint2 p0 = __ldg(&h16[s0 * 32 + l]);
            uint2 p1 = __ldg(&h16[s1 * 32 + l]);
            uint2 p2 = __ldg(&h16[s2 * 32 + l]);
            uint2 p3 = __ldg(&h16[s3 * 32 + l]);
            den += (e0 + e1) + (e2 + e3);
            float2 a0 = __half22float2(*(__half2*)&p0.x), b0 = __half22float2(*(__half2*)&p0.y);
            float2 a1 = __half22float2(*(__half2*)&p1.x), b1v = __half22float2(*(__half2*)&p1.y);
            float2 a2 = __half22float2(*(__half2*)&p2.x), b2v = __half22float2(*(__half2*)&p2.y);
            float2 a3 = __half22float2(*(__half2*)&p3.x), b3 = __half22float2(*(__half2*)&p3.y);
            acc.x += e0 * a0.x + e1 * a1.x + e2 * a2.x + e3 * a3.x;
            acc.y += e0 * a0.y + e1 * a1.y + e2 * a2.y + e3 * a3.y;
            acc.z += e0 * b0.x + e1 * b1v.x + e2 * b2v.x + e3 * b3.x;
            acc.w += e0 * b0.y + e1 * b1v.y + e2 * b2v.y + e3 * b3.y;
        }
        for (; k < je; k++) {
            int s = __shfl_sync(FULL, sj, k);
            float e = leaky_exp(__ldg(&g_as1[s * 8 + head]) + adp);
            den += e;
            uint2 p = __ldg(&h16[s * 32 + l]);
            float2 a = __half22float2(*(__half2*)&p.x);
            float2 b = __half22float2(*(__half2*)&p.y);
            acc.x += e * a.x; acc.y += e * a.y;
            acc.z += e * b.x; acc.w += e * b.y;
        }
    }
    const float rinv = 1.f / (den + EPSV);
    float4 v = ((const float4*)b1)[l];
    v.x += acc.x * rinv; v.y += acc.y * rinv;
    v.z += acc.z * rinv; v.w += acc.w * rinv;
    v.x = v.x > 0.f ? v.x : __expf(v.x) - 1.f;
    v.y = v.y > 0.f ? v.y : __expf(v.y) - 1.f;
    v.z = v.z > 0.f ? v.z : __expf(v.z) - 1.f;
    v.w = v.w > 0.f ? v.w : __expf(v.w) - 1.f;
    g_out1[n * 32 + l] = v;
}

// ---------------- 3. GEMM2: g2 = elu_h @ W2 [128->40] + scalar alphas -------
__global__ __launch_bounds__(256) void gemm2_kernel(
    const float* __restrict__ W2, const float* __restrict__ a_src,
    const float* __restrict__ a_dst)
{
    __shared__ float4 sW[128 * 10];
    __shared__ float4 sas[10], sad[10];
    __shared__ float  sx[256 * 17];
    const int tid = threadIdx.x;
    const int node = blockIdx.x * 256 + tid;
    const float4* W4 = (const float4*)W2;
    #pragma unroll
    for (int it = 0; it < 5; it++) sW[tid + it * 256] = W4[tid + it * 256];
    if (tid < 10) { sas[tid] = ((const float4*)a_src)[tid];
                    sad[tid] = ((const float4*)a_dst)[tid]; }
    const float* hin = (const float*)g_out1;

    float4 acc[10];
    #pragma unroll
    for (int j = 0; j < 10; j++) acc[j] = make_float4(0, 0, 0, 0);

    for (int kc = 0; kc < 8; kc++) {
        __syncthreads();
        #pragma unroll
        for (int it = 0; it < 16; it++) {
            int f = tid + it * 256;
            int nl2 = f >> 4, k = f & 15;
            int gn = blockIdx.x * 256 + nl2;
            sx[nl2 * 17 + k] = (gn < NN) ? hin[(size_t)gn * 128 + kc * 16 + k] : 0.f;
        }
        __syncthreads();
        #pragma unroll
        for (int k = 0; k < 16; k++) {
            float xv = sx[tid * 17 + k];
            const float4* wr = &sW[(kc * 16 + k) * 10];
            #pragma unroll
            for (int j = 0; j < 10; j++) fma4(acc[j], xv, wr[j]);
        }
    }
    if (node < NN) {
        float s = 0.f, d = 0.f;
        #pragma unroll
        for (int j = 0; j < 10; j++) { s += dot4(acc[j], sas[j]); d += dot4(acc[j], sad[j]); }
        #pragma unroll
        for (int j = 0; j < 10; j++) g_g2[node * 10 + j] = acc[j];
        g_as2[node] = s;
        g_ad2[node] = d;
    }
}

// ---------------- 4. L2 fused aggregate (one pass) + bias + log_softmax -----
__global__ __launch_bounds__(256) void agg2_kernel(
    const float* __restrict__ b2, float* __restrict__ out)
{
    const int n = (blockIdx.x * 256 + threadIdx.x) >> 5;
    const int l = threadIdx.x & 31;
    const int beg = g_off[n], end = g_off[n + 1];
    const float ad2n = g_ad2[n];
    const bool act = l < 10;

    float den = 0.f;
    float4 acc = make_float4(0.f, 0.f, 0.f, 0.f);

    for (int base = beg; base < end; base += 32) {
        const int je = min(32, end - base);
        const int sj = (l < je) ? __ldg(&g_ssrc[base + l]) : 0;
        int k = 0;
        #pragma unroll 1
        for (; k + 4 <= je; k += 4) {
            int s0 = __shfl_sync(FULL, sj, k);
            int s1 = __shfl_sync(FULL, sj, k + 1);
            int s2 = __shfl_sync(FULL, sj, k + 2);
            int s3 = __shfl_sync(FULL, sj, k + 3);
            float e0 = leaky_exp(__ldg(&g_as2[s0]) + ad2n);
            float e1 = leaky_exp(__ldg(&g_as2[s1]) + ad2n);
            float e2 = leaky_exp(__ldg(&g_as2[s2]) + ad2n);
            float e3 = leaky_exp(__ldg(&g_as2[s3]) + ad2n);
            den += (e0 + e1) + (e2 + e3);
            if (act) {
                fma4(acc, e0, g_g2[s0 * 10 + l]);
                fma4(acc, e1, g_g2[s1 * 10 + l]);
                fma4(acc, e2, g_g2[s2 * 10 + l]);
                fma4(acc, e3, g_g2[s3 * 10 + l]);
            }
        }
        for (; k < je; k++) {
            int s = __shfl_sync(FULL, sj, k);
            float e = leaky_exp(__ldg(&g_as2[s]) + ad2n);
            den += e;
            if (act) fma4(acc, e, g_g2[s * 10 + l]);
        }
    }
    const float rinv = 1.f / (den + EPSV);

    float4 v = make_float4(-1e30f, -1e30f, -1e30f, -1e30f);
    if (act) {
        v = ((const float4*)b2)[l];
        v.x += acc.x * rinv; v.y += acc.y * rinv;
        v.z += acc.z * rinv; v.w += acc.w * rinv;
    }
    float mx = act ? fmaxf(fmaxf(v.x, v.y), fmaxf(v.z, v.w)) : -1e30f;
    #pragma unroll
    for (int o = 16; o; o >>= 1) mx = fmaxf(mx, __shfl_xor_sync(FULL, mx, o));
    float sm = 0.f;
    if (act) sm = __expf(v.x - mx) + __expf(v.y - mx) + __expf(v.z - mx) + __expf(v.w - mx);
    #pragma unroll
    for (int o = 16; o; o >>= 1) sm += __shfl_xor_sync(FULL, sm, o);
    float lse = mx + logf(sm);
    if (act)
        ((float4*)out)[n * 10 + l] =
            make_float4(v.x - lse, v.y - lse, v.z - lse, v.w - lse);
}

// ---------------- launch ----------------
extern "C" void kernel_launch(void* const* d_in, const int* in_sizes, int n_in,
                              void* d_out, int out_size)
{
    const float* x      = (const float*)d_in[0];
    const int*   eidx   = (const int*)d_in[1];
    const float* W1     = (const float*)d_in[2];
    const float* a_src1 = (const float*)d_in[3];
    const float* a_dst1 = (const float*)d_in[4];
    const float* b1     = (const float*)d_in[5];
    const float* W2     = (const float*)d_in[6];
    const float* a_src2 = (const float*)d_in[7];
    const float* a_dst2 = (const float*)d_in[8];
    const float* b2     = (const float*)d_in[9];
    const int* src = eidx;
    const int* dst = eidx + EE;
    float* out = (float*)d_out;

    const int G1_SMEM = (128 * 128 + 64 * 128) * 4;   // 96 KB
    (void)cudaFuncSetAttribute(gemm1_kernel,
                               cudaFuncAttributeMaxDynamicSharedMemorySize, G1_SMEM);

    zero_kernel<<<(NN + 255) / 256, 256>>>();                      // 1
    hist_kernel<<<EE / 256, 256>>>(dst);                           // 2
    scan1_kernel<<<98, 1024>>>();                                  // 3
    gemm1_kernel<<<(NN + 63) / 64, 256, G1_SMEM>>>(x, W1, a_src1, a_dst1); // 4 (ncu)
    scanB_kernel<<<98, 1024>>>();                                  // 5
    scatter_kernel<<<EE / 256, 256>>>(src, dst);                   // 6
    agg1_kernel<<<NN / 8, 256>>>(b1);                              // 7
    gemm2_kernel<<<(NN + 255) / 256, 256>>>(W2, a_src2, a_dst2);   // 8
    agg2_kernel<<<NN / 8, 256>>>(b2, out);                         // 9
}

// round 9
// speedup vs baseline: 1.4810x; 1.0886x over previous
#include <cuda_runtime.h>
#include <cuda_fp16.h>
#include <math.h>

#define NN 100000
#define EE 1600000
#define EPSV 1e-16f
#define NEG_SLOPE 0.2f
#define FULL 0xffffffffu

// ---------------- scratch (device globals; allocation-free) ----------------
__device__ __half2 g_h1h[NN * 64];     // h1 [N,128] fp16       25.6 MB
__device__ float   g_as1[NN * 8];      // alpha_src1 [N,8]       3.2 MB
__device__ float   g_ad1[NN * 8];      // alpha_dst1 [N,8]       3.2 MB
__device__ __half2 g_out1h[NN * 64];   // elu(out1) [N,128] fp16 25.6 MB
__device__ __half2 g_g2h[NN * 20];     // g2 [N,40] fp16           8 MB
__device__ float   g_as2[NN];          // alpha_src2 [N]
__device__ float   g_ad2[NN];          // alpha_dst2 [N]
// CSR sort scratch
__device__ int     g_deg[NN];
__device__ int     g_off[NN + 1];
__device__ int     g_pos[NN];
__device__ int     g_ssrc[EE];         // src sorted by dst      6.4 MB
__device__ int     g_bsum[128];

// ---------------- helpers ----------------
__device__ __forceinline__ void fma4(float4& a, float s, float4 b) {
    a.x += s * b.x; a.y += s * b.y; a.z += s * b.z; a.w += s * b.w;
}
__device__ __forceinline__ float dot4(float4 a, float4 b) {
    return a.x * b.x + a.y * b.y + a.z * b.z + a.w * b.w;
}
__device__ __forceinline__ float leaky_exp(float e) {
    float t = e > 0.f ? e : NEG_SLOPE * e;
    return __expf(t);
}
__device__ __forceinline__ uint2 pack_half4(float4 v) {
    __half2 p0 = __floats2half2_rn(v.x, v.y);
    __half2 p1 = __floats2half2_rn(v.z, v.w);
    return make_uint2(*(unsigned*)&p0, *(unsigned*)&p1);
}

// ---------------- 0. zero sort counters ----------------
__global__ __launch_bounds__(256) void zero_kernel() {
    int i = blockIdx.x * 256 + threadIdx.x;
    if (i < NN) { g_deg[i] = 0; g_pos[i] = 0; }
}

// ---------------- S1. histogram of dst ----------------
__global__ __launch_bounds__(256) void hist_kernel(const int* __restrict__ dst) {
    int i = blockIdx.x * 256 + threadIdx.x;
    atomicAdd(&g_deg[__ldcs(dst + i)], 1);
}

// ---------------- S2a. block-level exclusive scan of degrees ----------------
__global__ __launch_bounds__(1024) void scan1_kernel() {
    int t = threadIdx.x;
    int i = blockIdx.x * 1024 + t;
    int v = (i < NN) ? g_deg[i] : 0;
    int lane = t & 31, w = t >> 5;
    int x = v;
    #pragma unroll
    for (int o = 1; o < 32; o <<= 1) {
        int y = __shfl_up_sync(FULL, x, o);
        if (lane >= o) x += y;
    }
    __shared__ int wt[32];
    if (lane == 31) wt[w] = x;
    __syncthreads();
    if (w == 0) {
        int z = wt[lane];
        #pragma unroll
        for (int o = 1; o < 32; o <<= 1) {
            int y = __shfl_up_sync(FULL, z, o);
            if (lane >= o) z += y;
        }
        wt[lane] = z;
    }
    __syncthreads();
    int pre = (w ? wt[w - 1] : 0);
    if (i < NN) g_off[i] = pre + x - v;      // block-local exclusive
    if (t == 1023) g_bsum[blockIdx.x] = wt[31];
}

// ---------------- S2b. add block prefix ----------------
__global__ __launch_bounds__(1024) void scanB_kernel() {
    __shared__ int s[128];
    __shared__ int blockpre;
    int t = threadIdx.x;
    if (t < 128) s[t] = (t < 98) ? g_bsum[t] : 0;
    __syncthreads();
    if (t == 0) {
        int run = 0;
        for (int b = 0; b < blockIdx.x; b++) run += s[b];
        blockpre = run;
    }
    __syncthreads();
    int i = blockIdx.x * 1024 + t;
    if (i < NN) g_off[i] += blockpre;
    if (i == 0) g_off[NN] = EE;
}

// ---------------- S3. scatter src into CSR order ----------------
__global__ __launch_bounds__(256) void scatter_kernel(
    const int* __restrict__ src, const int* __restrict__ dst)
{
    int i = blockIdx.x * 256 + threadIdx.x;
    int d = __ldcs(dst + i);
    int s = __ldcs(src + i);
    int p = g_off[d] + atomicAdd(&g_pos[d], 1);
    __stcs(&g_ssrc[p], s);
}

// ---------------- 1. GEMM1 (register-tiled, K-chunked): h1(fp16)=x@W1 -------
// Block: 64 nodes x 128 cols. 256 threads, 8n x 4c register tile each.
// Smem: sW chunk [64k x 128c] 32 KB + sx [64n x 128k] 32 KB = 64 KB
// -> 3 blocks/SM (was 2 at 96 KB).
__global__ __launch_bounds__(256) void gemm1_kernel(
    const float* __restrict__ x, const float* __restrict__ W1,
    const float* __restrict__ a_src, const float* __restrict__ a_dst)
{
    extern __shared__ float smem[];
    float4* sW4 = (float4*)smem;                 // [k*32 + c4] (64 k-rows)
    float4* sx4 = (float4*)(smem + 64 * 128);    // [n*32 + k4]
    const int tid = threadIdx.x;
    const int cx = tid & 31;      // col quad
    const int ny = tid >> 5;      // node group of 8
    const int nbase = blockIdx.x * 64;
    const float4* W4 = (const float4*)W1;
    const float4* x4 = (const float4*)x;

    #pragma unroll
    for (int it = 0; it < 8; it++) {             // x: 2048 f4
        int f = tid + it * 256;
        int gn = nbase + (f >> 5);
        sx4[f] = (gn < NN) ? x4[(size_t)gn * 32 + (f & 31)]
                           : make_float4(0.f, 0.f, 0.f, 0.f);
    }

    float4 c[8];
    #pragma unroll
    for (int i = 0; i < 8; i++) c[i] = make_float4(0.f, 0.f, 0.f, 0.f);

    #pragma unroll
    for (int ch = 0; ch < 2; ch++) {
        if (ch) __syncthreads();                 // drain reads of prev sW
        #pragma unroll
        for (int it = 0; it < 8; it++) {         // W chunk: 2048 f4
            int f = tid + it * 256;
            sW4[f] = W4[(ch * 64 + (f >> 5)) * 32 + (f & 31)];
        }
        __syncthreads();
        #pragma unroll 4
        for (int k = 0; k < 64; k += 4) {
            float4 w0 = sW4[(k + 0) * 32 + cx];
            float4 w1 = sW4[(k + 1) * 32 + cx];
            float4 w2 = sW4[(k + 2) * 32 + cx];
            float4 w3 = sW4[(k + 3) * 32 + cx];
            #pragma unroll
            for (int i = 0; i < 8; i++) {
                float4 xv = sx4[(ny * 8 + i) * 32 + ((ch * 64 + k) >> 2)];
                fma4(c[i], xv.x, w0); fma4(c[i], xv.y, w1);
                fma4(c[i], xv.z, w2); fma4(c[i], xv.w, w3);
            }
        }
    }

    // epilogue: store h1 (fp16) + per-head alpha dots
    const int head = cx >> 2, cq = cx & 3;
    const float4 asv = ((const float4*)a_src)[head * 4 + cq];
    const float4 adv = ((const float4*)a_dst)[head * 4 + cq];
    #pragma unroll
    for (int i = 0; i < 8; i++) {
        int gn = nbase + ny * 8 + i;
        float ps = dot4(c[i], asv);
        float pd = dot4(c[i], adv);
        ps += __shfl_xor_sync(FULL, ps, 1); ps += __shfl_xor_sync(FULL, ps, 2);
        pd += __shfl_xor_sync(FULL, pd, 1); pd += __shfl_xor_sync(FULL, pd, 2);
        if (gn < NN) {
            *(uint2*)&g_h1h[gn * 64 + 2 * cx] = pack_half4(c[i]);
            if (cq == 0) { g_as1[gn * 8 + head] = ps; g_ad1[gn * 8 + head] = pd; }
        }
    }
}

// ---------------- 2. L1 fused aggregate: warp per node, one pass, fp16 ------
__global__ __launch_bounds__(256) void agg1_kernel(const float* __restrict__ b1)
{
    const int n = (blockIdx.x * 256 + threadIdx.x) >> 5;   // node (grid exact)
    const int l = threadIdx.x & 31;
    const int beg = g_off[n], end = g_off[n + 1];
    const int head = l >> 2;
    const float adp = g_ad1[n * 8 + head];
    const uint2* h16 = (const uint2*)g_h1h;      // [n*32 + l] -> 4 halves

    float den = 0.f;
    float4 acc = make_float4(0.f, 0.f, 0.f, 0.f);

    for (int base = beg; base < end; base += 32) {
        const int je = min(32, end - base);
        const int sj = (l < je) ? __ldg(&g_ssrc[base + l]) : 0;
        int k = 0;
        #pragma unroll 1
        for (; k + 4 <= je; k += 4) {
            int s0 = __shfl_sync(FULL, sj, k);
            int s1 = __shfl_sync(FULL, sj, k + 1);
            int s2 = __shfl_sync(FULL, sj, k + 2);
            int s3 = __shfl_sync(FULL, sj, k + 3);
            float e0 = leaky_exp(__ldg(&g_as1[s0 * 8 + head]) + adp);
            float e1 = leaky_exp(__ldg(&g_as1[s1 * 8 + head]) + adp);
            float e2 = leaky_exp(__ldg(&g_as1[s2 * 8 + head]) + adp);
            float e3 = leaky_exp(__ldg(&g_as1[s3 * 8 + head]) + adp);
            uint2 p0 = __ldg(&h16[s0 * 32 + l]);
            uint2 p1 = __ldg(&h16[s1 * 32 + l]);
            uint2 p2 = __ldg(&h16[s2 * 32 + l]);
            uint2 p3 = __ldg(&h16[s3 * 32 + l]);
            den += (e0 + e1) + (e2 + e3);
            float2 a0 = __half22float2(*(__half2*)&p0.x), b0 = __half22float2(*(__half2*)&p0.y);
            float2 a1 = __half22float2(*(__half2*)&p1.x), b1v = __half22float2(*(__half2*)&p1.y);
            float2 a2 = __half22float2(*(__half2*)&p2.x), b2v = __half22float2(*(__half2*)&p2.y);
            float2 a3 = __half22float2(*(__half2*)&p3.x), b3 = __half22float2(*(__half2*)&p3.y);
            acc.x += e0 * a0.x + e1 * a1.x + e2 * a2.x + e3 * a3.x;
            acc.y += e0 * a0.y + e1 * a1.y + e2 * a2.y + e3 * a3.y;
            acc.z += e0 * b0.x + e1 * b1v.x + e2 * b2v.x + e3 * b3.x;
            acc.w += e0 * b0.y + e1 * b1v.y + e2 * b2v.y + e3 * b3.y;
        }
        for (; k < je; k++) {
            int s = __shfl_sync(FULL, sj, k);
            float e = leaky_exp(__ldg(&g_as1[s * 8 + head]) + adp);
            den += e;
            uint2 p = __ldg(&h16[s * 32 + l]);
            float2 a = __half22float2(*(__half2*)&p.x);
            float2 b = __half22float2(*(__half2*)&p.y);
            acc.x += e * a.x; acc.y += e * a.y;
            acc.z += e * b.x; acc.w += e * b.y;
        }
    }
    const float rinv = 1.f / (den + EPSV);
    float4 v = ((const float4*)b1)[l];
    v.x += acc.x * rinv; v.y += acc.y * rinv;
    v.z += acc.z * rinv; v.w += acc.w * rinv;
    v.x = v.x > 0.f ? v.x : __expf(v.x) - 1.f;
    v.y = v.y > 0.f ? v.y : __expf(v.y) - 1.f;
    v.z = v.z > 0.f ? v.z : __expf(v.z) - 1.f;
    v.w = v.w > 0.f ? v.w : __expf(v.w) - 1.f;
    *(uint2*)&g_out1h[n * 64 + 2 * l] = pack_half4(v);     // fp16 store
}

// ---------------- 3. GEMM2: g2(fp16) = elu_h(fp16) @ W2 + scalar alphas -----
__global__ __launch_bounds__(256) void gemm2_kernel(
    const float* __restrict__ W2, const float* __restrict__ a_src,
    const float* __restrict__ a_dst)
{
    __shared__ float4 sW[128 * 10];
    __shared__ float4 sas[10], sad[10];
    __shared__ float  sx[256 * 17];
    const int tid = threadIdx.x;
    const int node = blockIdx.x * 256 + tid;
    const float4* W4 = (const float4*)W2;
    #pragma unroll
    for (int it = 0; it < 5; it++) sW[tid + it * 256] = W4[tid + it * 256];
    if (tid < 10) { sas[tid] = ((const float4*)a_src)[tid];
                    sad[tid] = ((const float4*)a_dst)[tid]; }
    const __half2* hin2 = g_out1h;

    float4 acc[10];
    #pragma unroll
    for (int j = 0; j < 10; j++) acc[j] = make_float4(0, 0, 0, 0);

    for (int kc = 0; kc < 8; kc++) {
        __syncthreads();
        #pragma unroll
        for (int it = 0; it < 8; it++) {             // 256 nodes x 8 half2
            int f = tid + it * 256;
            int nl2 = f >> 3, kp = f & 7;
            int gn = blockIdx.x * 256 + nl2;
            float2 fv = make_float2(0.f, 0.f);
            if (gn < NN) fv = __half22float2(hin2[(size_t)gn * 64 + kc * 8 + kp]);
            sx[nl2 * 17 + kp * 2 + 0] = fv.x;
            sx[nl2 * 17 + kp * 2 + 1] = fv.y;
        }
        __syncthreads();
        #pragma unroll
        for (int k = 0; k < 16; k++) {
            float xv = sx[tid * 17 + k];
            const float4* wr = &sW[(kc * 16 + k) * 10];
            #pragma unroll
            for (int j = 0; j < 10; j++) fma4(acc[j], xv, wr[j]);
        }
    }
    if (node < NN) {
        float s = 0.f, d = 0.f;
        #pragma unroll
        for (int j = 0; j < 10; j++) { s += dot4(acc[j], sas[j]); d += dot4(acc[j], sad[j]); }
        #pragma unroll
        for (int j = 0; j < 10; j++)
            *(uint2*)&g_g2h[node * 20 + 2 * j] = pack_half4(acc[j]);
        g_as2[node] = s;
        g_ad2[node] = d;
    }
}

// ---------------- 4. L2 fused aggregate (one pass, fp16 g2) + log_softmax ---
__global__ __launch_bounds__(256) void agg2_kernel(
    const float* __restrict__ b2, float* __restrict__ out)
{
    const int n = (blockIdx.x * 256 + threadIdx.x) >> 5;
    const int l = threadIdx.x & 31;
    const int beg = g_off[n], end = g_off[n + 1];
    const float ad2n = g_ad2[n];
    const bool act = l < 10;
    const uint2* g24 = (const uint2*)g_g2h;      // [n*10 + l] -> 4 halves

    float den = 0.f;
    float4 acc = make_float4(0.f, 0.f, 0.f, 0.f);

    for (int base = beg; base < end; base += 32) {
        const int je = min(32, end - base);
        const int sj = (l < je) ? __ldg(&g_ssrc[base + l]) : 0;
        int k = 0;
        #pragma unroll 1
        for (; k + 4 <= je; k += 4) {
            int s0 = __shfl_sync(FULL, sj, k);
            int s1 = __shfl_sync(FULL, sj, k + 1);
            int s2 = __shfl_sync(FULL, sj, k + 2);
            int s3 = __shfl_sync(FULL, sj, k + 3);
            float e0 = leaky_exp(__ldg(&g_as2[s0]) + ad2n);
            float e1 = leaky_exp(__ldg(&g_as2[s1]) + ad2n);
            float e2 = leaky_exp(__ldg(&g_as2[s2]) + ad2n);
            float e3 = leaky_exp(__ldg(&g_as2[s3]) + ad2n);
            den += (e0 + e1) + (e2 + e3);
            if (act) {
                uint2 p0 = __ldg(&g24[s0 * 10 + l]);
                uint2 p1 = __ldg(&g24[s1 * 10 + l]);
                uint2 p2 = __ldg(&g24[s2 * 10 + l]);
                uint2 p3 = __ldg(&g24[s3 * 10 + l]);
                float2 a0 = __half22float2(*(__half2*)&p0.x), b0 = __half22float2(*(__half2*)&p0.y);
                float2 a1 = __half22float2(*(__half2*)&p1.x), b1v = __half22float2(*(__half2*)&p1.y);
                float2 a2 = __half22float2(*(__half2*)&p2.x), b2v = __half22float2(*(__half2*)&p2.y);
                float2 a3 = __half22float2(*(__half2*)&p3.x), b3 = __half22float2(*(__half2*)&p3.y);
                acc.x += e0 * a0.x + e1 * a1.x + e2 * a2.x + e3 * a3.x;
                acc.y += e0 * a0.y + e1 * a1.y + e2 * a2.y + e3 * a3.y;
                acc.z += e0 * b0.x + e1 * b1v.x + e2 * b2v.x + e3 * b3.x;
                acc.w += e0 * b0.y + e1 * b1v.y + e2 * b2v.y + e3 * b3.y;
            }
        }
        for (; k < je; k++) {
            int s = __shfl_sync(FULL, sj, k);
            float e = leaky_exp(__ldg(&g_as2[s]) + ad2n);
            den += e;
            if (act) {
                uint2 p = __ldg(&g24[s * 10 + l]);
                float2 a = __half22float2(*(__half2*)&p.x);
                float2 b = __half22float2(*(__half2*)&p.y);
                acc.x += e * a.x; acc.y += e * a.y;
                acc.z += e * b.x; acc.w += e * b.y;
            }
        }
    }
    const float rinv = 1.f / (den + EPSV);

    float4 v = make_float4(-1e30f, -1e30f, -1e30f, -1e30f);
    if (act) {
        v = ((const float4*)b2)[l];
        v.x += acc.x * rinv; v.y += acc.y * rinv;
        v.z += acc.z * rinv; v.w += acc.w * rinv;
    }
    float mx = act ? fmaxf(fmaxf(v.x, v.y), fmaxf(v.z, v.w)) : -1e30f;
    #pragma unroll
    for (int o = 16; o; o >>= 1) mx = fmaxf(mx, __shfl_xor_sync(FULL, mx, o));
    float sm = 0.f;
    if (act) sm = __expf(v.x - mx) + __expf(v.y - mx) + __expf(v.z - mx) + __expf(v.w - mx);
    #pragma unroll
    for (int o = 16; o; o >>= 1) sm += __shfl_xor_sync(FULL, sm, o);
    float lse = mx + logf(sm);
    if (act)
        ((float4*)out)[n * 10 + l] =
            make_float4(v.x - lse, v.y - lse, v.z - lse, v.w - lse);
}

// ---------------- launch ----------------
extern "C" void kernel_launch(void* const* d_in, const int* in_sizes, int n_in,
                              void* d_out, int out_size)
{
    const float* x      = (const float*)d_in[0];
    const int*   eidx   = (const int*)d_in[1];
    const float* W1     = (const float*)d_in[2];
    const float* a_src1 = (const float*)d_in[3];
    const float* a_dst1 = (const float*)d_in[4];
    const float* b1     = (const float*)d_in[5];
    const float* W2     = (const float*)d_in[6];
    const float* a_src2 = (const float*)d_in[7];
    const float* a_dst2 = (const float*)d_in[8];
    const float* b2     = (const float*)d_in[9];
    const int* src = eidx;
    const int* dst = eidx + EE;
    float* out = (float*)d_out;

    const int G1_SMEM = (64 * 128 + 64 * 128) * 4;   // 64 KB
    (void)cudaFuncSetAttribute(gemm1_kernel,
                               cudaFuncAttributeMaxDynamicSharedMemorySize, G1_SMEM);

    zero_kernel<<<(NN + 255) / 256, 256>>>();                      // 1
    hist_kernel<<<EE / 256, 256>>>(dst);                           // 2
    scan1_kernel<<<98, 1024>>>();                                  // 3
    gemm1_kernel<<<(NN + 63) / 64, 256, G1_SMEM>>>(x, W1, a_src1, a_dst1); // 4 (ncu)
    scanB_kernel<<<98, 1024>>>();                                  // 5
    scatter_kernel<<<EE / 256, 256>>>(src, dst);                   // 6
    agg1_kernel<<<NN / 8, 256>>>(b1);                              // 7
    gemm2_kernel<<<(NN + 255) / 256, 256>>>(W2, a_src2, a_dst2);   // 8
    agg2_kernel<<<NN / 8, 256>>>(b2, out);                         // 9
}

// round 10
// speedup vs baseline: 1.5310x; 1.0337x over previous
#include <cuda_runtime.h>
#include <cuda_fp16.h>
#include <math.h>

#define NN 100000
#define EE 1600000
#define EPSV 1e-16f
#define NEG_SLOPE 0.2f
#define FULL 0xffffffffu

// ---------------- scratch (device globals; allocation-free) ----------------
__device__ __half2 g_h1h[NN * 64];     // h1 [N,128] fp16       25.6 MB
__device__ float   g_as1[NN * 8];      // alpha_src1 [N,8]       3.2 MB
__device__ float   g_ad1[NN * 8];      // alpha_dst1 [N,8]       3.2 MB
__device__ __half2 g_out1h[NN * 64];   // elu(out1) [N,128] fp16 25.6 MB
__device__ __half2 g_g2h[NN * 20];     // g2 [N,40] fp16           8 MB
__device__ float   g_as2[NN];          // alpha_src2 [N]
__device__ float   g_ad2[NN];          // alpha_dst2 [N]
// CSR sort scratch
__device__ int     g_deg[NN];
__device__ int     g_off[NN + 1];
__device__ int     g_pos[NN];
__device__ int     g_ssrc[EE];         // src sorted by dst      6.4 MB
__device__ int     g_bsum[128];

// ---------------- helpers ----------------
__device__ __forceinline__ void fma4(float4& a, float s, float4 b) {
    a.x += s * b.x; a.y += s * b.y; a.z += s * b.z; a.w += s * b.w;
}
__device__ __forceinline__ float dot4(float4 a, float4 b) {
    return a.x * b.x + a.y * b.y + a.z * b.z + a.w * b.w;
}
__device__ __forceinline__ float leaky_exp(float e) {
    float t = e > 0.f ? e : NEG_SLOPE * e;
    return __expf(t);
}
__device__ __forceinline__ uint2 pack_half4(float4 v) {
    __half2 p0 = __floats2half2_rn(v.x, v.y);
    __half2 p1 = __floats2half2_rn(v.z, v.w);
    return make_uint2(*(unsigned*)&p0, *(unsigned*)&p1);
}

// ---------------- 0. zero sort counters ----------------
__global__ __launch_bounds__(256) void zero_kernel() {
    int i = blockIdx.x * 256 + threadIdx.x;
    if (i < NN) { g_deg[i] = 0; g_pos[i] = 0; }
}

// ---------------- S1. histogram of dst ----------------
__global__ __launch_bounds__(256) void hist_kernel(const int* __restrict__ dst) {
    int i = blockIdx.x * 256 + threadIdx.x;
    atomicAdd(&g_deg[__ldcs(dst + i)], 1);
}

// ---------------- S2a. block-level exclusive scan of degrees ----------------
__global__ __launch_bounds__(1024) void scan1_kernel() {
    int t = threadIdx.x;
    int i = blockIdx.x * 1024 + t;
    int v = (i < NN) ? g_deg[i] : 0;
    int lane = t & 31, w = t >> 5;
    int x = v;
    #pragma unroll
    for (int o = 1; o < 32; o <<= 1) {
        int y = __shfl_up_sync(FULL, x, o);
        if (lane >= o) x += y;
    }
    __shared__ int wt[32];
    if (lane == 31) wt[w] = x;
    __syncthreads();
    if (w == 0) {
        int z = wt[lane];
        #pragma unroll
        for (int o = 1; o < 32; o <<= 1) {
            int y = __shfl_up_sync(FULL, z, o);
            if (lane >= o) z += y;
        }
        wt[lane] = z;
    }
    __syncthreads();
    int pre = (w ? wt[w - 1] : 0);
    if (i < NN) g_off[i] = pre + x - v;      // block-local exclusive
    if (t == 1023) g_bsum[blockIdx.x] = wt[31];
}

// ---------------- S2b. add block prefix ----------------
__global__ __launch_bounds__(1024) void scanB_kernel() {
    __shared__ int s[128];
    __shared__ int blockpre;
    int t = threadIdx.x;
    if (t < 128) s[t] = (t < 98) ? g_bsum[t] : 0;
    __syncthreads();
    if (t == 0) {
        int run = 0;
        for (int b = 0; b < blockIdx.x; b++) run += s[b];
        blockpre = run;
    }
    __syncthreads();
    int i = blockIdx.x * 1024 + t;
    if (i < NN) g_off[i] += blockpre;
    if (i == 0) g_off[NN] = EE;
}

// ---------------- S3. scatter src into CSR order ----------------
__global__ __launch_bounds__(256) void scatter_kernel(
    const int* __restrict__ src, const int* __restrict__ dst)
{
    int i = blockIdx.x * 256 + threadIdx.x;
    int d = __ldcs(dst + i);
    int s = __ldcs(src + i);
    int p = g_off[d] + atomicAdd(&g_pos[d], 1);
    __stcs(&g_ssrc[p], s);
}

// ---------------- 1. GEMM1 (register-tiled, K-chunked): h1(fp16)=x@W1 -------
// Block: 64 nodes x 128 cols. 256 threads, 8n x 4c register tile each.
// Smem: sW chunk [64k x 128c] 32 KB + sx [64n x 128k] 32 KB = 64 KB.
__global__ __launch_bounds__(256) void gemm1_kernel(
    const float* __restrict__ x, const float* __restrict__ W1,
    const float* __restrict__ a_src, const float* __restrict__ a_dst)
{
    extern __shared__ float smem[];
    float4* sW4 = (float4*)smem;                 // [k*32 + c4] (64 k-rows)
    float4* sx4 = (float4*)(smem + 64 * 128);    // [n*32 + k4]
    const int tid = threadIdx.x;
    const int cx = tid & 31;      // col quad
    const int ny = tid >> 5;      // node group of 8
    const int nbase = blockIdx.x * 64;
    const float4* W4 = (const float4*)W1;
    const float4* x4 = (const float4*)x;

    #pragma unroll
    for (int it = 0; it < 8; it++) {             // x: 2048 f4
        int f = tid + it * 256;
        int gn = nbase + (f >> 5);
        sx4[f] = (gn < NN) ? x4[(size_t)gn * 32 + (f & 31)]
                           : make_float4(0.f, 0.f, 0.f, 0.f);
    }

    float4 c[8];
    #pragma unroll
    for (int i = 0; i < 8; i++) c[i] = make_float4(0.f, 0.f, 0.f, 0.f);

    #pragma unroll
    for (int ch = 0; ch < 2; ch++) {
        if (ch) __syncthreads();                 // drain reads of prev sW
        #pragma unroll
        for (int it = 0; it < 8; it++) {         // W chunk: 2048 f4
            int f = tid + it * 256;
            sW4[f] = W4[(ch * 64 + (f >> 5)) * 32 + (f & 31)];
        }
        __syncthreads();
        #pragma unroll 4
        for (int k = 0; k < 64; k += 4) {
            float4 w0 = sW4[(k + 0) * 32 + cx];
            float4 w1 = sW4[(k + 1) * 32 + cx];
            float4 w2 = sW4[(k + 2) * 32 + cx];
            float4 w3 = sW4[(k + 3) * 32 + cx];
            #pragma unroll
            for (int i = 0; i < 8; i++) {
                float4 xv = sx4[(ny * 8 + i) * 32 + ((ch * 64 + k) >> 2)];
                fma4(c[i], xv.x, w0); fma4(c[i], xv.y, w1);
                fma4(c[i], xv.z, w2); fma4(c[i], xv.w, w3);
            }
        }
    }

    // epilogue: store h1 (fp16) + per-head alpha dots
    const int head = cx >> 2, cq = cx & 3;
    const float4 asv = ((const float4*)a_src)[head * 4 + cq];
    const float4 adv = ((const float4*)a_dst)[head * 4 + cq];
    #pragma unroll
    for (int i = 0; i < 8; i++) {
        int gn = nbase + ny * 8 + i;
        float ps = dot4(c[i], asv);
        float pd = dot4(c[i], adv);
        ps += __shfl_xor_sync(FULL, ps, 1); ps += __shfl_xor_sync(FULL, ps, 2);
        pd += __shfl_xor_sync(FULL, pd, 1); pd += __shfl_xor_sync(FULL, pd, 2);
        if (gn < NN) {
            *(uint2*)&g_h1h[gn * 64 + 2 * cx] = pack_half4(c[i]);
            if (cq == 0) { g_as1[gn * 8 + head] = ps; g_ad1[gn * 8 + head] = pd; }
        }
    }
}

// ---------------- 2. L1 fused aggregate: warp per node, one pass, fp16 ------
__global__ __launch_bounds__(256) void agg1_kernel(const float* __restrict__ b1)
{
    const int n = (blockIdx.x * 256 + threadIdx.x) >> 5;   // node (grid exact)
    const int l = threadIdx.x & 31;
    const int beg = g_off[n], end = g_off[n + 1];
    const int head = l >> 2;
    const float adp = g_ad1[n * 8 + head];
    const uint2* h16 = (const uint2*)g_h1h;      // [n*32 + l] -> 4 halves

    float den = 0.f;
    float4 acc = make_float4(0.f, 0.f, 0.f, 0.f);

    for (int base = beg; base < end; base += 32) {
        const int je = min(32, end - base);
        const int sj = (l < je) ? __ldg(&g_ssrc[base + l]) : 0;
        int k = 0;
        #pragma unroll 1
        for (; k + 4 <= je; k += 4) {
            int s0 = __shfl_sync(FULL, sj, k);
            int s1 = __shfl_sync(FULL, sj, k + 1);
            int s2 = __shfl_sync(FULL, sj, k + 2);
            int s3 = __shfl_sync(FULL, sj, k + 3);
            float e0 = leaky_exp(__ldg(&g_as1[s0 * 8 + head]) + adp);
            float e1 = leaky_exp(__ldg(&g_as1[s1 * 8 + head]) + adp);
            float e2 = leaky_exp(__ldg(&g_as1[s2 * 8 + head]) + adp);
            float e3 = leaky_exp(__ldg(&g_as1[s3 * 8 + head]) + adp);
            uint2 p0 = __ldg(&h16[s0 * 32 + l]);
            uint2 p1 = __ldg(&h16[s1 * 32 + l]);
            uint2 p2 = __ldg(&h16[s2 * 32 + l]);
            uint2 p3 = __ldg(&h16[s3 * 32 + l]);
            den += (e0 + e1) + (e2 + e3);
            float2 a0 = __half22float2(*(__half2*)&p0.x), b0 = __half22float2(*(__half2*)&p0.y);
            float2 a1 = __half22float2(*(__half2*)&p1.x), b1v = __half22float2(*(__half2*)&p1.y);
            float2 a2 = __half22float2(*(__half2*)&p2.x), b2v = __half22float2(*(__half2*)&p2.y);
            float2 a3 = __half22float2(*(__half2*)&p3.x), b3 = __half22float2(*(__half2*)&p3.y);
            acc.x += e0 * a0.x + e1 * a1.x + e2 * a2.x + e3 * a3.x;
            acc.y += e0 * a0.y + e1 * a1.y + e2 * a2.y + e3 * a3.y;
            acc.z += e0 * b0.x + e1 * b1v.x + e2 * b2v.x + e3 * b3.x;
            acc.w += e0 * b0.y + e1 * b1v.y + e2 * b2v.y + e3 * b3.y;
        }
        for (; k < je; k++) {
            int s = __shfl_sync(FULL, sj, k);
            float e = leaky_exp(__ldg(&g_as1[s * 8 + head]) + adp);
            den += e;
            uint2 p = __ldg(&h16[s * 32 + l]);
            float2 a = __half22float2(*(__half2*)&p.x);
            float2 b = __half22float2(*(__half2*)&p.y);
            acc.x += e * a.x; acc.y += e * a.y;
            acc.z += e * b.x; acc.w += e * b.y;
        }
    }
    const float rinv = 1.f / (den + EPSV);
    float4 v = ((const float4*)b1)[l];
    v.x += acc.x * rinv; v.y += acc.y * rinv;
    v.z += acc.z * rinv; v.w += acc.w * rinv;
    v.x = v.x > 0.f ? v.x : __expf(v.x) - 1.f;
    v.y = v.y > 0.f ? v.y : __expf(v.y) - 1.f;
    v.z = v.z > 0.f ? v.z : __expf(v.z) - 1.f;
    v.w = v.w > 0.f ? v.w : __expf(v.w) - 1.f;
    *(uint2*)&g_out1h[n * 64 + 2 * l] = pack_half4(v);     // fp16 store
}

// ---------------- 3. GEMM2: g2(fp16) = elu_h(fp16) @ W2 + scalar alphas -----
__global__ __launch_bounds__(256) void gemm2_kernel(
    const float* __restrict__ W2, const float* __restrict__ a_src,
    const float* __restrict__ a_dst)
{
    __shared__ float4 sW[128 * 10];
    __shared__ float4 sas[10], sad[10];
    __shared__ float  sx[256 * 17];
    const int tid = threadIdx.x;
    const int node = blockIdx.x * 256 + tid;
    const float4* W4 = (const float4*)W2;
    #pragma unroll
    for (int it = 0; it < 5; it++) sW[tid + it * 256] = W4[tid + it * 256];
    if (tid < 10) { sas[tid] = ((const float4*)a_src)[tid];
                    sad[tid] = ((const float4*)a_dst)[tid]; }
    const __half2* hin2 = g_out1h;

    float4 acc[10];
    #pragma unroll
    for (int j = 0; j < 10; j++) acc[j] = make_float4(0, 0, 0, 0);

    for (int kc = 0; kc < 8; kc++) {
        __syncthreads();
        #pragma unroll
        for (int it = 0; it < 8; it++) {             // 256 nodes x 8 half2
            int f = tid + it * 256;
            int nl2 = f >> 3, kp = f & 7;
            int gn = blockIdx.x * 256 + nl2;
            float2 fv = make_float2(0.f, 0.f);
            if (gn < NN) fv = __half22float2(hin2[(size_t)gn * 64 + kc * 8 + kp]);
            sx[nl2 * 17 + kp * 2 + 0] = fv.x;
            sx[nl2 * 17 + kp * 2 + 1] = fv.y;
        }
        __syncthreads();
        #pragma unroll
        for (int k = 0; k < 16; k++) {
            float xv = sx[tid * 17 + k];
            const float4* wr = &sW[(kc * 16 + k) * 10];
            #pragma unroll
            for (int j = 0; j < 10; j++) fma4(acc[j], xv, wr[j]);
        }
    }
    if (node < NN) {
        float s = 0.f, d = 0.f;
        #pragma unroll
        for (int j = 0; j < 10; j++) { s += dot4(acc[j], sas[j]); d += dot4(acc[j], sad[j]); }
        #pragma unroll
        for (int j = 0; j < 10; j++)
            *(uint2*)&g_g2h[node * 20 + 2 * j] = pack_half4(acc[j]);
        g_as2[node] = s;
        g_ad2[node] = d;
    }
}

// ---------------- 4. L2 fused aggregate (one pass, fp16 g2) + log_softmax ---
__global__ __launch_bounds__(256) void agg2_kernel(
    const float* __restrict__ b2, float* __restrict__ out)
{
    const int n = (blockIdx.x * 256 + threadIdx.x) >> 5;
    const int l = threadIdx.x & 31;
    const int beg = g_off[n], end = g_off[n + 1];
    const float ad2n = g_ad2[n];
    const bool act = l < 10;
    const uint2* g24 = (const uint2*)g_g2h;      // [n*10 + l] -> 4 halves

    float den = 0.f;
    float4 acc = make_float4(0.f, 0.f, 0.f, 0.f);

    for (int base = beg; base < end; base += 32) {
        const int je = min(32, end - base);
        const int sj = (l < je) ? __ldg(&g_ssrc[base + l]) : 0;
        int k = 0;
        #pragma unroll 1
        for (; k + 4 <= je; k += 4) {
            int s0 = __shfl_sync(FULL, sj, k);
            int s1 = __shfl_sync(FULL, sj, k + 1);
            int s2 = __shfl_sync(FULL, sj, k + 2);
            int s3 = __shfl_sync(FULL, sj, k + 3);
            float e0 = leaky_exp(__ldg(&g_as2[s0]) + ad2n);
            float e1 = leaky_exp(__ldg(&g_as2[s1]) + ad2n);
            float e2 = leaky_exp(__ldg(&g_as2[s2]) + ad2n);
            float e3 = leaky_exp(__ldg(&g_as2[s3]) + ad2n);
            den += (e0 + e1) + (e2 + e3);
            if (act) {
                uint2 p0 = __ldg(&g24[s0 * 10 + l]);
                uint2 p1 = __ldg(&g24[s1 * 10 + l]);
                uint2 p2 = __ldg(&g24[s2 * 10 + l]);
                uint2 p3 = __ldg(&g24[s3 * 10 + l]);
                float2 a0 = __half22float2(*(__half2*)&p0.x), b0 = __half22float2(*(__half2*)&p0.y);
                float2 a1 = __half22float2(*(__half2*)&p1.x), b1v = __half22float2(*(__half2*)&p1.y);
                float2 a2 = __half22float2(*(__half2*)&p2.x), b2v = __half22float2(*(__half2*)&p2.y);
                float2 a3 = __half22float2(*(__half2*)&p3.x), b3 = __half22float2(*(__half2*)&p3.y);
                acc.x += e0 * a0.x + e1 * a1.x + e2 * a2.x + e3 * a3.x;
                acc.y += e0 * a0.y + e1 * a1.y + e2 * a2.y + e3 * a3.y;
                acc.z += e0 * b0.x + e1 * b1v.x + e2 * b2v.x + e3 * b3.x;
                acc.w += e0 * b0.y + e1 * b1v.y + e2 * b2v.y + e3 * b3.y;
            }
        }
        for (; k < je; k++) {
            int s = __shfl_sync(FULL, sj, k);
            float e = leaky_exp(__ldg(&g_as2[s]) + ad2n);
            den += e;
            if (act) {
                uint2 p = __ldg(&g24[s * 10 + l]);
                float2 a = __half22float2(*(__half2*)&p.x);
                float2 b = __half22float2(*(__half2*)&p.y);
                acc.x += e * a.x; acc.y += e * a.y;
                acc.z += e * b.x; acc.w += e * b.y;
            }
        }
    }
    const float rinv = 1.f / (den + EPSV);

    float4 v = make_float4(-1e30f, -1e30f, -1e30f, -1e30f);
    if (act) {
        v = ((const float4*)b2)[l];
        v.x += acc.x * rinv; v.y += acc.y * rinv;
        v.z += acc.z * rinv; v.w += acc.w * rinv;
    }
    float mx = act ? fmaxf(fmaxf(v.x, v.y), fmaxf(v.z, v.w)) : -1e30f;
    #pragma unroll
    for (int o = 16; o; o >>= 1) mx = fmaxf(mx, __shfl_xor_sync(FULL, mx, o));
    float sm = 0.f;
    if (act) sm = __expf(v.x - mx) + __expf(v.y - mx) + __expf(v.z - mx) + __expf(v.w - mx);
    #pragma unroll
    for (int o = 16; o; o >>= 1) sm += __shfl_xor_sync(FULL, sm, o);
    float lse = mx + logf(sm);
    if (act)
        ((float4*)out)[n * 10 + l] =
            make_float4(v.x - lse, v.y - lse, v.z - lse, v.w - lse);
}

// ---------------- launch ----------------
extern "C" void kernel_launch(void* const* d_in, const int* in_sizes, int n_in,
                              void* d_out, int out_size)
{
    const float* x      = (const float*)d_in[0];
    const int*   eidx   = (const int*)d_in[1];
    const float* W1     = (const float*)d_in[2];
    const float* a_src1 = (const float*)d_in[3];
    const float* a_dst1 = (const float*)d_in[4];
    const float* b1     = (const float*)d_in[5];
    const float* W2     = (const float*)d_in[6];
    const float* a_src2 = (const float*)d_in[7];
    const float* a_dst2 = (const float*)d_in[8];
    const float* b2     = (const float*)d_in[9];
    const int* src = eidx;
    const int* dst = eidx + EE;
    float* out = (float*)d_out;

    // Side stream + events for fork/join overlap of the CSR build with gemm1.
    // Resource init only (no work caching): created once, before any capture.
    static cudaStream_t sB = nullptr;
    static cudaEvent_t evFork = nullptr, evJoin = nullptr;
    if (sB == nullptr) {
        cudaStreamCreateWithFlags(&sB, cudaStreamNonBlocking);
        cudaEventCreateWithFlags(&evFork, cudaEventDisableTiming);
        cudaEventCreateWithFlags(&evJoin, cudaEventDisableTiming);
    }

    const int G1_SMEM = (64 * 128 + 64 * 128) * 4;   // 64 KB
    (void)cudaFuncSetAttribute(gemm1_kernel,
                               cudaFuncAttributeMaxDynamicSharedMemorySize, G1_SMEM);

    // fork: sort chain on sB runs concurrently with gemm1 on the main stream
    cudaEventRecord(evFork, 0);
    cudaStreamWaitEvent(sB, evFork, 0);

    gemm1_kernel<<<(NN + 63) / 64, 256, G1_SMEM>>>(x, W1, a_src1, a_dst1); // main
    zero_kernel<<<(NN + 255) / 256, 256, 0, sB>>>();
    hist_kernel<<<EE / 256, 256, 0, sB>>>(dst);
    scan1_kernel<<<98, 1024, 0, sB>>>();
    scanB_kernel<<<98, 1024, 0, sB>>>();
    scatter_kernel<<<EE / 256, 256, 0, sB>>>(src, dst);

    // join: agg1 needs both gemm1 outputs and the CSR
    cudaEventRecord(evJoin, sB);
    cudaStreamWaitEvent(0, evJoin, 0);

    agg1_kernel<<<NN / 8, 256>>>(b1);
    gemm2_kernel<<<(NN + 255) / 256, 256>>>(W2, a_src2, a_dst2);
    agg2_kernel<<<NN / 8, 256>>>(b2, out);
}

// round 11
// speedup vs baseline: 1.5390x; 1.0052x over previous
#include <cuda_runtime.h>
#include <cuda_fp16.h>
#include <math.h>

#define NN 100000
#define EE 1600000
#define EPSV 1e-16f
#define NEG_SLOPE 0.2f
#define FULL 0xffffffffu

// ---------------- scratch (device globals; allocation-free) ----------------
__device__ __half2 g_h1h[NN * 64];     // h1 [N,128] fp16       25.6 MB
__device__ float   g_as1[NN * 8];      // alpha_src1 [N,8]       3.2 MB
__device__ float   g_ad1[NN * 8];      // alpha_dst1 [N,8]       3.2 MB
__device__ __half2 g_out1h[NN * 64];   // elu(out1) [N,128] fp16 25.6 MB
__device__ __half2 g_g2h[NN * 20];     // g2 [N,40] fp16           8 MB
__device__ float   g_as2[NN];          // alpha_src2 [N]
__device__ float   g_ad2[NN];          // alpha_dst2 [N]
// CSR sort scratch
__device__ int     g_deg[NN];
__device__ int     g_off[NN + 1];
__device__ int     g_pos[NN];
__device__ int     g_ssrc[EE];         // src sorted by dst      6.4 MB
__device__ int     g_bsum[128];

// ---------------- helpers ----------------
__device__ __forceinline__ void fma4(float4& a, float s, float4 b) {
    a.x += s * b.x; a.y += s * b.y; a.z += s * b.z; a.w += s * b.w;
}
__device__ __forceinline__ float dot4(float4 a, float4 b) {
    return a.x * b.x + a.y * b.y + a.z * b.z + a.w * b.w;
}
__device__ __forceinline__ float leaky_exp(float e) {
    float t = e > 0.f ? e : NEG_SLOPE * e;
    return __expf(t);
}
__device__ __forceinline__ uint2 pack_half4(float4 v) {
    __half2 p0 = __floats2half2_rn(v.x, v.y);
    __half2 p1 = __floats2half2_rn(v.z, v.w);
    return make_uint2(*(unsigned*)&p0, *(unsigned*)&p1);
}
// ---- packed fp32x2 (Blackwell FFMA2) ----
__device__ __forceinline__ unsigned long long pk2(float lo, float hi) {
    unsigned long long r;
    asm("mov.b64 %0, {%1, %2};" : "=l"(r) : "f"(lo), "f"(hi));
    return r;
}
__device__ __forceinline__ unsigned long long fma2(
    unsigned long long a, unsigned long long b, unsigned long long c) {
    unsigned long long d;
    asm("fma.rn.f32x2 %0, %1, %2, %3;" : "=l"(d) : "l"(a), "l"(b), "l"(c));
    return d;
}
__device__ __forceinline__ float2 upk2(unsigned long long v) {
    float2 f;
    asm("mov.b64 {%0, %1}, %2;" : "=f"(f.x), "=f"(f.y) : "l"(v));
    return f;
}

// ---------------- 0. zero sort counters ----------------
__global__ __launch_bounds__(256) void zero_kernel() {
    int i = blockIdx.x * 256 + threadIdx.x;
    if (i < NN) { g_deg[i] = 0; g_pos[i] = 0; }
}

// ---------------- S1. histogram of dst ----------------
__global__ __launch_bounds__(256) void hist_kernel(const int* __restrict__ dst) {
    int i = blockIdx.x * 256 + threadIdx.x;
    atomicAdd(&g_deg[__ldcs(dst + i)], 1);
}

// ---------------- S2a. block-level exclusive scan of degrees ----------------
__global__ __launch_bounds__(1024) void scan1_kernel() {
    int t = threadIdx.x;
    int i = blockIdx.x * 1024 + t;
    int v = (i < NN) ? g_deg[i] : 0;
    int lane = t & 31, w = t >> 5;
    int x = v;
    #pragma unroll
    for (int o = 1; o < 32; o <<= 1) {
        int y = __shfl_up_sync(FULL, x, o);
        if (lane >= o) x += y;
    }
    __shared__ int wt[32];
    if (lane == 31) wt[w] = x;
    __syncthreads();
    if (w == 0) {
        int z = wt[lane];
        #pragma unroll
        for (int o = 1; o < 32; o <<= 1) {
            int y = __shfl_up_sync(FULL, z, o);
            if (lane >= o) z += y;
        }
        wt[lane] = z;
    }
    __syncthreads();
    int pre = (w ? wt[w - 1] : 0);
    if (i < NN) g_off[i] = pre + x - v;      // block-local exclusive
    if (t == 1023) g_bsum[blockIdx.x] = wt[31];
}

// ---------------- S2b. add block prefix ----------------
__global__ __launch_bounds__(1024) void scanB_kernel() {
    __shared__ int s[128];
    __shared__ int blockpre;
    int t = threadIdx.x;
    if (t < 128) s[t] = (t < 98) ? g_bsum[t] : 0;
    __syncthreads();
    if (t == 0) {
        int run = 0;
        for (int b = 0; b < blockIdx.x; b++) run += s[b];
        blockpre = run;
    }
    __syncthreads();
    int i = blockIdx.x * 1024 + t;
    if (i < NN) g_off[i] += blockpre;
    if (i == 0) g_off[NN] = EE;
}

// ---------------- S3. scatter src into CSR order ----------------
__global__ __launch_bounds__(256) void scatter_kernel(
    const int* __restrict__ src, const int* __restrict__ dst)
{
    int i = blockIdx.x * 256 + threadIdx.x;
    int d = __ldcs(dst + i);
    int s = __ldcs(src + i);
    int p = g_off[d] + atomicAdd(&g_pos[d], 1);
    __stcs(&g_ssrc[p], s);
}

// ---------------- 1. GEMM1 (register-tiled, f32x2): h1(fp16)=x@W1 -----------
// Block: 64 nodes x 128 cols. 256 threads, 8n x 4c register tile each.
// Inner loop uses fma.rn.f32x2: W tiles read as ulonglong2 (zero-cost),
// x broadcast packed once per (i,k).
__global__ __launch_bounds__(256) void gemm1_kernel(
    const float* __restrict__ x, const float* __restrict__ W1,
    const float* __restrict__ a_src, const float* __restrict__ a_dst)
{
    extern __shared__ float smem[];
    float4* sW4 = (float4*)smem;                 // [k*32 + c4] (64 k-rows)
    float4* sx4 = (float4*)(smem + 64 * 128);    // [n*32 + k4]
    const ulonglong2* sW2 = (const ulonglong2*)smem;
    const int tid = threadIdx.x;
    const int cx = tid & 31;      // col quad
    const int ny = tid >> 5;      // node group of 8
    const int nbase = blockIdx.x * 64;
    const float4* W4 = (const float4*)W1;
    const float4* x4 = (const float4*)x;

    #pragma unroll
    for (int it = 0; it < 8; it++) {             // x: 2048 f4
        int f = tid + it * 256;
        int gn = nbase + (f >> 5);
        sx4[f] = (gn < NN) ? x4[(size_t)gn * 32 + (f & 31)]
                           : make_float4(0.f, 0.f, 0.f, 0.f);
    }

    unsigned long long c2[8][2];
    #pragma unroll
    for (int i = 0; i < 8; i++) { c2[i][0] = 0ull; c2[i][1] = 0ull; }

    #pragma unroll
    for (int ch = 0; ch < 2; ch++) {
        if (ch) __syncthreads();                 // drain reads of prev sW
        #pragma unroll
        for (int it = 0; it < 8; it++) {         // W chunk: 2048 f4
            int f = tid + it * 256;
            sW4[f] = W4[(ch * 64 + (f >> 5)) * 32 + (f & 31)];
        }
        __syncthreads();
        #pragma unroll 4
        for (int k = 0; k < 64; k += 4) {
            ulonglong2 w0 = sW2[(k + 0) * 32 + cx];
            ulonglong2 w1 = sW2[(k + 1) * 32 + cx];
            ulonglong2 w2 = sW2[(k + 2) * 32 + cx];
            ulonglong2 w3 = sW2[(k + 3) * 32 + cx];
            #pragma unroll
            for (int i = 0; i < 8; i++) {
                float4 xv = sx4[(ny * 8 + i) * 32 + ((ch * 64 + k) >> 2)];
                unsigned long long d0 = pk2(xv.x, xv.x);
                unsigned long long d1 = pk2(xv.y, xv.y);
                unsigned long long d2 = pk2(xv.z, xv.z);
                unsigned long long d3 = pk2(xv.w, xv.w);
                c2[i][0] = fma2(d0, w0.x, c2[i][0]);
                c2[i][1] = fma2(d0, w0.y, c2[i][1]);
                c2[i][0] = fma2(d1, w1.x, c2[i][0]);
                c2[i][1] = fma2(d1, w1.y, c2[i][1]);
                c2[i][0] = fma2(d2, w2.x, c2[i][0]);
                c2[i][1] = fma2(d2, w2.y, c2[i][1]);
                c2[i][0] = fma2(d3, w3.x, c2[i][0]);
                c2[i][1] = fma2(d3, w3.y, c2[i][1]);
            }
        }
    }

    // epilogue: unpack, store h1 (fp16) + per-head alpha dots
    const int head = cx >> 2, cq = cx & 3;
    const float4 asv = ((const float4*)a_src)[head * 4 + cq];
    const float4 adv = ((const float4*)a_dst)[head * 4 + cq];
    #pragma unroll
    for (int i = 0; i < 8; i++) {
        int gn = nbase + ny * 8 + i;
        float2 lo = upk2(c2[i][0]);
        float2 hi = upk2(c2[i][1]);
        float4 ci = make_float4(lo.x, lo.y, hi.x, hi.y);
        float ps = dot4(ci, asv);
        float pd = dot4(ci, adv);
        ps += __shfl_xor_sync(FULL, ps, 1); ps += __shfl_xor_sync(FULL, ps, 2);
        pd += __shfl_xor_sync(FULL, pd, 1); pd += __shfl_xor_sync(FULL, pd, 2);
        if (gn < NN) {
            *(uint2*)&g_h1h[gn * 64 + 2 * cx] = pack_half4(ci);
            if (cq == 0) { g_as1[gn * 8 + head] = ps; g_ad1[gn * 8 + head] = pd; }
        }
    }
}

// ---------------- 2. L1 fused aggregate: warp per node, one pass, fp16 ------
__global__ __launch_bounds__(256) void agg1_kernel(const float* __restrict__ b1)
{
    const int n = (blockIdx.x * 256 + threadIdx.x) >> 5;   // node (grid exact)
    const int l = threadIdx.x & 31;
    const int beg = g_off[n], end = g_off[n + 1];
    const int head = l >> 2;
    const float adp = g_ad1[n * 8 + head];
    const uint2* h16 = (const uint2*)g_h1h;      // [n*32 + l] -> 4 halves

    float den = 0.f;
    float4 acc = make_float4(0.f, 0.f, 0.f, 0.f);

    for (int base = beg; base < end; base += 32) {
        const int je = min(32, end - base);
        const int sj = (l < je) ? __ldg(&g_ssrc[base + l]) : 0;
        int k = 0;
        #pragma unroll 1
        for (; k + 4 <= je; k += 4) {
            int s0 = __shfl_sync(FULL, sj, k);
            int s1 = __shfl_sync(FULL, sj, k + 1);
            int s2 = __shfl_sync(FULL, sj, k + 2);
            int s3 = __shfl_sync(FULL, sj, k + 3);
            float e0 = leaky_exp(__ldg(&g_as1[s0 * 8 + head]) + adp);
            float e1 = leaky_exp(__ldg(&g_as1[s1 * 8 + head]) + adp);
            float e2 = leaky_exp(__ldg(&g_as1[s2 * 8 + head]) + adp);
            float e3 = leaky_exp(__ldg(&g_as1[s3 * 8 + head]) + adp);
            uint2 p0 = __ldg(&h16[s0 * 32 + l]);
            uint2 p1 = __ldg(&h16[s1 * 32 + l]);
            uint2 p2 = __ldg(&h16[s2 * 32 + l]);
            uint2 p3 = __ldg(&h16[s3 * 32 + l]);
            den += (e0 + e1) + (e2 + e3);
            float2 a0 = __half22float2(*(__half2*)&p0.x), b0 = __half22float2(*(__half2*)&p0.y);
            float2 a1 = __half22float2(*(__half2*)&p1.x), b1v = __half22float2(*(__half2*)&p1.y);
            float2 a2 = __half22float2(*(__half2*)&p2.x), b2v = __half22float2(*(__half2*)&p2.y);
            float2 a3 = __half22float2(*(__half2*)&p3.x), b3 = __half22float2(*(__half2*)&p3.y);
            acc.x += e0 * a0.x + e1 * a1.x + e2 * a2.x + e3 * a3.x;
            acc.y += e0 * a0.y + e1 * a1.y + e2 * a2.y + e3 * a3.y;
            acc.z += e0 * b0.x + e1 * b1v.x + e2 * b2v.x + e3 * b3.x;
            acc.w += e0 * b0.y + e1 * b1v.y + e2 * b2v.y + e3 * b3.y;
        }
        for (; k < je; k++) {
            int s = __shfl_sync(FULL, sj, k);
            float e = leaky_exp(__ldg(&g_as1[s * 8 + head]) + adp);
            den += e;
            uint2 p = __ldg(&h16[s * 32 + l]);
            float2 a = __half22float2(*(__half2*)&p.x);
            float2 b = __half22float2(*(__half2*)&p.y);
            acc.x += e * a.x; acc.y += e * a.y;
            acc.z += e * b.x; acc.w += e * b.y;
        }
    }
    const float rinv = 1.f / (den + EPSV);
    float4 v = ((const float4*)b1)[l];
    v.x += acc.x * rinv; v.y += acc.y * rinv;
    v.z += acc.z * rinv; v.w += acc.w * rinv;
    v.x = v.x > 0.f ? v.x : __expf(v.x) - 1.f;
    v.y = v.y > 0.f ? v.y : __expf(v.y) - 1.f;
    v.z = v.z > 0.f ? v.z : __expf(v.z) - 1.f;
    v.w = v.w > 0.f ? v.w : __expf(v.w) - 1.f;
    *(uint2*)&g_out1h[n * 64 + 2 * l] = pack_half4(v);     // fp16 store
}

// ---------------- 3. GEMM2 (f32x2): g2(fp16) = elu_h(fp16) @ W2 + alphas ----
__global__ __launch_bounds__(256) void gemm2_kernel(
    const float* __restrict__ W2, const float* __restrict__ a_src,
    const float* __restrict__ a_dst)
{
    __shared__ float4 sW[128 * 10];
    __shared__ float4 sas[10], sad[10];
    __shared__ float  sx[256 * 17];
    const int tid = threadIdx.x;
    const int node = blockIdx.x * 256 + tid;
    const float4* W4 = (const float4*)W2;
    const ulonglong2* sW2p = (const ulonglong2*)sW;
    #pragma unroll
    for (int it = 0; it < 5; it++) sW[tid + it * 256] = W4[tid + it * 256];
    if (tid < 10) { sas[tid] = ((const float4*)a_src)[tid];
                    sad[tid] = ((const float4*)a_dst)[tid]; }
    const __half2* hin2 = g_out1h;

    unsigned long long acc2[10][2];
    #pragma unroll
    for (int j = 0; j < 10; j++) { acc2[j][0] = 0ull; acc2[j][1] = 0ull; }

    for (int kc = 0; kc < 8; kc++) {
        __syncthreads();
        #pragma unroll
        for (int it = 0; it < 8; it++) {             // 256 nodes x 8 half2
            int f = tid + it * 256;
            int nl2 = f >> 3, kp = f & 7;
            int gn = blockIdx.x * 256 + nl2;
            float2 fv = make_float2(0.f, 0.f);
            if (gn < NN) fv = __half22float2(hin2[(size_t)gn * 64 + kc * 8 + kp]);
            sx[nl2 * 17 + kp * 2 + 0] = fv.x;
            sx[nl2 * 17 + kp * 2 + 1] = fv.y;
        }
        __syncthreads();
        #pragma unroll
        for (int k = 0; k < 16; k++) {
            float xv = sx[tid * 17 + k];
            unsigned long long xd = pk2(xv, xv);
            const ulonglong2* wr = &sW2p[(kc * 16 + k) * 10];
            #pragma unroll
            for (int j = 0; j < 10; j++) {
                ulonglong2 w = wr[j];
                acc2[j][0] = fma2(xd, w.x, acc2[j][0]);
                acc2[j][1] = fma2(xd, w.y, acc2[j][1]);
            }
        }
    }
    if (node < NN) {
        float s = 0.f, d = 0.f;
        float4 accf[10];
        #pragma unroll
        for (int j = 0; j < 10; j++) {
            float2 lo = upk2(acc2[j][0]);
            float2 hi = upk2(acc2[j][1]);
            accf[j] = make_float4(lo.x, lo.y, hi.x, hi.y);
            s += dot4(accf[j], sas[j]);
            d += dot4(accf[j], sad[j]);
        }
        #pragma unroll
        for (int j = 0; j < 10; j++)
            *(uint2*)&g_g2h[node * 20 + 2 * j] = pack_half4(accf[j]);
        g_as2[node] = s;
        g_ad2[node] = d;
    }
}

// ---------------- 4. L2 fused aggregate (one pass, fp16 g2) + log_softmax ---
__global__ __launch_bounds__(256) void agg2_kernel(
    const float* __restrict__ b2, float* __restrict__ out)
{
    const int n = (blockIdx.x * 256 + threadIdx.x) >> 5;
    const int l = threadIdx.x & 31;
    const int beg = g_off[n], end = g_off[n + 1];
    const float ad2n = g_ad2[n];
    const bool act = l < 10;
    const uint2* g24 = (const uint2*)g_g2h;      // [n*10 + l] -> 4 halves

    float den = 0.f;
    float4 acc = make_float4(0.f, 0.f, 0.f, 0.f);

    for (int base = beg; base < end; base += 32) {
        const int je = min(32, end - base);
        const int sj = (l < je) ? __ldg(&g_ssrc[base + l]) : 0;
        int k = 0;
        #pragma unroll 1
        for (; k + 4 <= je; k += 4) {
            int s0 = __shfl_sync(FULL, sj, k);
            int s1 = __shfl_sync(FULL, sj, k + 1);
            int s2 = __shfl_sync(FULL, sj, k + 2);
            int s3 = __shfl_sync(FULL, sj, k + 3);
            float e0 = leaky_exp(__ldg(&g_as2[s0]) + ad2n);
            float e1 = leaky_exp(__ldg(&g_as2[s1]) + ad2n);
            float e2 = leaky_exp(__ldg(&g_as2[s2]) + ad2n);
            float e3 = leaky_exp(__ldg(&g_as2[s3]) + ad2n);
            den += (e0 + e1) + (e2 + e3);
            if (act) {
                uint2 p0 = __ldg(&g24[s0 * 10 + l]);
                uint2 p1 = __ldg(&g24[s1 * 10 + l]);
                uint2 p2 = __ldg(&g24[s2 * 10 + l]);
                uint2 p3 = __ldg(&g24[s3 * 10 + l]);
                float2 a0 = __half22float2(*(__half2*)&p0.x), b0 = __half22float2(*(__half2*)&p0.y);
                float2 a1 = __half22float2(*(__half2*)&p1.x), b1v = __half22float2(*(__half2*)&p1.y);
                float2 a2 = __half22float2(*(__half2*)&p2.x), b2v = __half22float2(*(__half2*)&p2.y);
                float2 a3 = __half22float2(*(__half2*)&p3.x), b3 = __half22float2(*(__half2*)&p3.y);
                acc.x += e0 * a0.x + e1 * a1.x + e2 * a2.x + e3 * a3.x;
                acc.y += e0 * a0.y + e1 * a1.y + e2 * a2.y + e3 * a3.y;
                acc.z += e0 * b0.x + e1 * b1v.x + e2 * b2v.x + e3 * b3.x;
                acc.w += e0 * b0.y + e1 * b1v.y + e2 * b2v.y + e3 * b3.y;
            }
        }
        for (; k < je; k++) {
            int s = __shfl_sync(FULL, sj, k);
            float e = leaky_exp(__ldg(&g_as2[s]) + ad2n);
            den += e;
            if (act) {
                uint2 p = __ldg(&g24[s * 10 + l]);
                float2 a = __half22float2(*(__half2*)&p.x);
                float2 b = __half22float2(*(__half2*)&p.y);
                acc.x += e * a.x; acc.y += e * a.y;
                acc.z += e * b.x; acc.w += e * b.y;
            }
        }
    }
    const float rinv = 1.f / (den + EPSV);

    float4 v = make_float4(-1e30f, -1e30f, -1e30f, -1e30f);
    if (act) {
        v = ((const float4*)b2)[l];
        v.x += acc.x * rinv; v.y += acc.y * rinv;
        v.z += acc.z * rinv; v.w += acc.w * rinv;
    }
    float mx = act ? fmaxf(fmaxf(v.x, v.y), fmaxf(v.z, v.w)) : -1e30f;
    #pragma unroll
    for (int o = 16; o; o >>= 1) mx = fmaxf(mx, __shfl_xor_sync(FULL, mx, o));
    float sm = 0.f;
    if (act) sm = __expf(v.x - mx) + __expf(v.y - mx) + __expf(v.z - mx) + __expf(v.w - mx);
    #pragma unroll
    for (int o = 16; o; o >>= 1) sm += __shfl_xor_sync(FULL, sm, o);
    float lse = mx + logf(sm);
    if (act)
        ((float4*)out)[n * 10 + l] =
            make_float4(v.x - lse, v.y - lse, v.z - lse, v.w - lse);
}

// ---------------- launch ----------------
extern "C" void kernel_launch(void* const* d_in, const int* in_sizes, int n_in,
                              void* d_out, int out_size)
{
    const float* x      = (const float*)d_in[0];
    const int*   eidx   = (const int*)d_in[1];
    const float* W1     = (const float*)d_in[2];
    const float* a_src1 = (const float*)d_in[3];
    const float* a_dst1 = (const float*)d_in[4];
    const float* b1     = (const float*)d_in[5];
    const float* W2     = (const float*)d_in[6];
    const float* a_src2 = (const float*)d_in[7];
    const float* a_dst2 = (const float*)d_in[8];
    const float* b2     = (const float*)d_in[9];
    const int* src = eidx;
    const int* dst = eidx + EE;
    float* out = (float*)d_out;

    // Side stream + events for fork/join overlap of the CSR build with gemm1.
    static cudaStream_t sB = nullptr;
    static cudaEvent_t evFork = nullptr, evJoin = nullptr;
    if (sB == nullptr) {
        cudaStreamCreateWithFlags(&sB, cudaStreamNonBlocking);
        cudaEventCreateWithFlags(&evFork, cudaEventDisableTiming);
        cudaEventCreateWithFlags(&evJoin, cudaEventDisableTiming);
    }

    const int G1_SMEM = (64 * 128 + 64 * 128) * 4;   // 64 KB
    (void)cudaFuncSetAttribute(gemm1_kernel,
                               cudaFuncAttributeMaxDynamicSharedMemorySize, G1_SMEM);

    // fork: sort chain on sB runs concurrently with gemm1 on the main stream
    cudaEventRecord(evFork, 0);
    cudaStreamWaitEvent(sB, evFork, 0);

    gemm1_kernel<<<(NN + 63) / 64, 256, G1_SMEM>>>(x, W1, a_src1, a_dst1); // main
    zero_kernel<<<(NN + 255) / 256, 256, 0, sB>>>();
    hist_kernel<<<EE / 256, 256, 0, sB>>>(dst);
    scan1_kernel<<<98, 1024, 0, sB>>>();
    scanB_kernel<<<98, 1024, 0, sB>>>();
    scatter_kernel<<<EE / 256, 256, 0, sB>>>(src, dst);

    // join: agg1 needs both gemm1 outputs and the CSR
    cudaEventRecord(evJoin, sB);
    cudaStreamWaitEvent(0, evJoin, 0);

    agg1_kernel<<<NN / 8, 256>>>(b1);
    gemm2_kernel<<<(NN + 255) / 256, 256>>>(W2, a_src2, a_dst2);
    agg2_kernel<<<NN / 8, 256>>>(b2, out);
}

// round 13
// speedup vs baseline: 1.6590x; 1.0780x over previous
#include <cuda_runtime.h>
#include <cuda_fp16.h>
#include <math.h>

#define NN 100000
#define EE 1600000
#define EPSV 1e-16f
#define NEG_SLOPE 0.2f
#define FULL 0xffffffffu

// ---------------- scratch (device globals; allocation-free) ----------------
__device__ __half2 g_h1h[NN * 64];     // h1 [N,128] fp16       25.6 MB
__device__ float   g_as1[NN * 8];      // alpha_src1 [N,8]       3.2 MB
__device__ float   g_ad1[NN * 8];      // alpha_dst1 [N,8]       3.2 MB
__device__ __half2 g_out1h[NN * 64];   // elu(out1) [N,128] fp16 25.6 MB
__device__ __half2 g_g2h[NN * 20];     // g2 [N,40] fp16           8 MB
__device__ float   g_as2[NN];          // alpha_src2 [N]
__device__ float   g_ad2[NN];          // alpha_dst2 [N]
// CSR sort scratch
__device__ int     g_deg[NN];
__device__ int     g_off[NN + 1];
__device__ int     g_pos[NN];
__device__ int     g_ssrc[EE];         // src sorted by dst      6.4 MB
__device__ int     g_bsum[128];

// ---------------- helpers ----------------
__device__ __forceinline__ void fma4(float4& a, float s, float4 b) {
    a.x += s * b.x; a.y += s * b.y; a.z += s * b.z; a.w += s * b.w;
}
__device__ __forceinline__ float dot4(float4 a, float4 b) {
    return a.x * b.x + a.y * b.y + a.z * b.z + a.w * b.w;
}
__device__ __forceinline__ float leaky_exp(float e) {
    float t = e > 0.f ? e : NEG_SLOPE * e;
    return __expf(t);
}
__device__ __forceinline__ uint2 pack_half4(float4 v) {
    __half2 p0 = __floats2half2_rn(v.x, v.y);
    __half2 p1 = __floats2half2_rn(v.z, v.w);
    return make_uint2(*(unsigned*)&p0, *(unsigned*)&p1);
}
// ---- packed fp32x2 (Blackwell FFMA2) ----
__device__ __forceinline__ unsigned long long pk2(float lo, float hi) {
    unsigned long long r;
    asm("mov.b64 %0, {%1, %2};" : "=l"(r) : "f"(lo), "f"(hi));
    return r;
}
__device__ __forceinline__ unsigned long long fma2(
    unsigned long long a, unsigned long long b, unsigned long long c) {
    unsigned long long d;
    asm("fma.rn.f32x2 %0, %1, %2, %3;" : "=l"(d) : "l"(a), "l"(b), "l"(c));
    return d;
}
__device__ __forceinline__ float2 upk2(unsigned long long v) {
    float2 f;
    asm("mov.b64 {%0, %1}, %2;" : "=f"(f.x), "=f"(f.y) : "l"(v));
    return f;
}

// ---------------- 0. zero sort counters ----------------
__global__ __launch_bounds__(256) void zero_kernel() {
    int i = blockIdx.x * 256 + threadIdx.x;
    if (i < NN) { g_deg[i] = 0; g_pos[i] = 0; }
}

// ---------------- S1. histogram of dst (4 edges/thread) ----------------
__global__ __launch_bounds__(256) void hist_kernel(const int* __restrict__ dst) {
    int i = blockIdx.x * 256 + threadIdx.x;
    if (i < EE / 4) {
        int4 d = __ldcs(&((const int4*)dst)[i]);
        atomicAdd(&g_deg[d.x], 1);
        atomicAdd(&g_deg[d.y], 1);
        atomicAdd(&g_deg[d.z], 1);
        atomicAdd(&g_deg[d.w], 1);
    }
}

// ---------------- S2a. block-level exclusive scan of degrees ----------------
__global__ __launch_bounds__(1024) void scan1_kernel() {
    int t = threadIdx.x;
    int i = blockIdx.x * 1024 + t;
    int v = (i < NN) ? g_deg[i] : 0;
    int lane = t & 31, w = t >> 5;
    int x = v;
    #pragma unroll
    for (int o = 1; o < 32; o <<= 1) {
        int y = __shfl_up_sync(FULL, x, o);
        if (lane >= o) x += y;
    }
    __shared__ int wt[32];
    if (lane == 31) wt[w] = x;
    __syncthreads();
    if (w == 0) {
        int z = wt[lane];
        #pragma unroll
        for (int o = 1; o < 32; o <<= 1) {
            int y = __shfl_up_sync(FULL, z, o);
            if (lane >= o) z += y;
        }
        wt[lane] = z;
    }
    __syncthreads();
    int pre = (w ? wt[w - 1] : 0);
    if (i < NN) g_off[i] = pre + x - v;      // block-local exclusive
    if (t == 1023) g_bsum[blockIdx.x] = wt[31];
}

// ---------------- S2b. add block prefix ----------------
__global__ __launch_bounds__(1024) void scanB_kernel() {
    __shared__ int s[128];
    __shared__ int blockpre;
    int t = threadIdx.x;
    if (t < 128) s[t] = (t < 98) ? g_bsum[t] : 0;
    __syncthreads();
    if (t == 0) {
        int run = 0;
        for (int b = 0; b < blockIdx.x; b++) run += s[b];
        blockpre = run;
    }
    __syncthreads();
    int i = blockIdx.x * 1024 + t;
    if (i < NN) g_off[i] += blockpre;
    if (i == 0) g_off[NN] = EE;
}

// ---------------- S3. scatter src into CSR order (4 edges/thread) -----------
__global__ __launch_bounds__(256) void scatter_kernel(
    const int* __restrict__ src, const int* __restrict__ dst)
{
    int i = blockIdx.x * 256 + threadIdx.x;
    if (i < EE / 4) {
        int4 d = __ldcs(&((const int4*)dst)[i]);
        int4 s = __ldcs(&((const int4*)src)[i]);
        int p0 = g_off[d.x] + atomicAdd(&g_pos[d.x], 1);
        int p1 = g_off[d.y] + atomicAdd(&g_pos[d.y], 1);
        int p2 = g_off[d.z] + atomicAdd(&g_pos[d.z], 1);
        int p3 = g_off[d.w] + atomicAdd(&g_pos[d.w], 1);
        __stcs(&g_ssrc[p0], s.x);
        __stcs(&g_ssrc[p1], s.y);
        __stcs(&g_ssrc[p2], s.z);
        __stcs(&g_ssrc[p3], s.w);
    }
}

// ---------------- 1. GEMM1 (register-tiled, f32x2): h1(fp16)=x@W1 -----------
__global__ __launch_bounds__(256) void gemm1_kernel(
    const float* __restrict__ x, const float* __restrict__ W1,
    const float* __restrict__ a_src, const float* __restrict__ a_dst)
{
    extern __shared__ float smem[];
    float4* sW4 = (float4*)smem;                 // [k*32 + c4] (64 k-rows)
    float4* sx4 = (float4*)(smem + 64 * 128);    // [n*32 + k4]
    const ulonglong2* sW2 = (const ulonglong2*)smem;
    const int tid = threadIdx.x;
    const int cx = tid & 31;      // col quad
    const int ny = tid >> 5;      // node group of 8
    const int nbase = blockIdx.x * 64;
    const float4* W4 = (const float4*)W1;
    const float4* x4 = (const float4*)x;

    #pragma unroll
    for (int it = 0; it < 8; it++) {             // x: 2048 f4
        int f = tid + it * 256;
        int gn = nbase + (f >> 5);
        sx4[f] = (gn < NN) ? x4[(size_t)gn * 32 + (f & 31)]
                           : make_float4(0.f, 0.f, 0.f, 0.f);
    }

    unsigned long long c2[8][2];
    #pragma unroll
    for (int i = 0; i < 8; i++) { c2[i][0] = 0ull; c2[i][1] = 0ull; }

    #pragma unroll
    for (int ch = 0; ch < 2; ch++) {
        if (ch) __syncthreads();                 // drain reads of prev sW
        #pragma unroll
        for (int it = 0; it < 8; it++) {         // W chunk: 2048 f4
            int f = tid + it * 256;
            sW4[f] = W4[(ch * 64 + (f >> 5)) * 32 + (f & 31)];
        }
        __syncthreads();
        #pragma unroll 4
        for (int k = 0; k < 64; k += 4) {
            ulonglong2 w0 = sW2[(k + 0) * 32 + cx];
            ulonglong2 w1 = sW2[(k + 1) * 32 + cx];
            ulonglong2 w2 = sW2[(k + 2) * 32 + cx];
            ulonglong2 w3 = sW2[(k + 3) * 32 + cx];
            #pragma unroll
            for (int i = 0; i < 8; i++) {
                float4 xv = sx4[(ny * 8 + i) * 32 + ((ch * 64 + k) >> 2)];
                unsigned long long d0 = pk2(xv.x, xv.x);
                unsigned long long d1 = pk2(xv.y, xv.y);
                unsigned long long d2 = pk2(xv.z, xv.z);
                unsigned long long d3 = pk2(xv.w, xv.w);
                c2[i][0] = fma2(d0, w0.x, c2[i][0]);
                c2[i][1] = fma2(d0, w0.y, c2[i][1]);
                c2[i][0] = fma2(d1, w1.x, c2[i][0]);
                c2[i][1] = fma2(d1, w1.y, c2[i][1]);
                c2[i][0] = fma2(d2, w2.x, c2[i][0]);
                c2[i][1] = fma2(d2, w2.y, c2[i][1]);
                c2[i][0] = fma2(d3, w3.x, c2[i][0]);
                c2[i][1] = fma2(d3, w3.y, c2[i][1]);
            }
        }
    }

    // epilogue: unpack, store h1 (fp16) + per-head alpha dots
    const int head = cx >> 2, cq = cx & 3;
    const float4 asv = ((const float4*)a_src)[head * 4 + cq];
    const float4 adv = ((const float4*)a_dst)[head * 4 + cq];
    #pragma unroll
    for (int i = 0; i < 8; i++) {
        int gn = nbase + ny * 8 + i;
        float2 lo = upk2(c2[i][0]);
        float2 hi = upk2(c2[i][1]);
        float4 ci = make_float4(lo.x, lo.y, hi.x, hi.y);
        float ps = dot4(ci, asv);
        float pd = dot4(ci, adv);
        ps += __shfl_xor_sync(FULL, ps, 1); ps += __shfl_xor_sync(FULL, ps, 2);
        pd += __shfl_xor_sync(FULL, pd, 1); pd += __shfl_xor_sync(FULL, pd, 2);
        if (gn < NN) {
            *(uint2*)&g_h1h[gn * 64 + 2 * cx] = pack_half4(ci);
            if (cq == 0) { g_as1[gn * 8 + head] = ps; g_ad1[gn * 8 + head] = pd; }
        }
    }
}

// ---------------- 2. L1 fused aggregate: warp per node, one pass, fp16 ------
__global__ __launch_bounds__(256) void agg1_kernel(const float* __restrict__ b1)
{
    const int n = (blockIdx.x * 256 + threadIdx.x) >> 5;   // node (grid exact)
    const int l = threadIdx.x & 31;
    const int beg = g_off[n], end = g_off[n + 1];
    const int head = l >> 2;
    const float adp = g_ad1[n * 8 + head];
    const uint2* h16 = (const uint2*)g_h1h;      // [n*32 + l] -> 4 halves

    float den = 0.f;
    float4 acc = make_float4(0.f, 0.f, 0.f, 0.f);

    for (int base = beg; base < end; base += 32) {
        const int je = min(32, end - base);
        const int sj = (l < je) ? __ldg(&g_ssrc[base + l]) : 0;
        int k = 0;
        #pragma unroll 1
        for (; k + 4 <= je; k += 4) {
            int s0 = __shfl_sync(FULL, sj, k);
            int s1 = __shfl_sync(FULL, sj, k + 1);
            int s2 = __shfl_sync(FULL, sj, k + 2);
            int s3 = __shfl_sync(FULL, sj, k + 3);
            float e0 = leaky_exp(__ldg(&g_as1[s0 * 8 + head]) + adp);
            float e1 = leaky_exp(__ldg(&g_as1[s1 * 8 + head]) + adp);
            float e2 = leaky_exp(__ldg(&g_as1[s2 * 8 + head]) + adp);
            float e3 = leaky_exp(__ldg(&g_as1[s3 * 8 + head]) + adp);
            uint2 p0 = __ldg(&h16[s0 * 32 + l]);
            uint2 p1 = __ldg(&h16[s1 * 32 + l]);
            uint2 p2 = __ldg(&h16[s2 * 32 + l]);
            uint2 p3 = __ldg(&h16[s3 * 32 + l]);
            den += (e0 + e1) + (e2 + e3);
            float2 a0 = __half22float2(*(__half2*)&p0.x), b0 = __half22float2(*(__half2*)&p0.y);
            float2 a1 = __half22float2(*(__half2*)&p1.x), b1v = __half22float2(*(__half2*)&p1.y);
            float2 a2 = __half22float2(*(__half2*)&p2.x), b2v = __half22float2(*(__half2*)&p2.y);
            float2 a3 = __half22float2(*(__half2*)&p3.x), b3 = __half22float2(*(__half2*)&p3.y);
            acc.x += e0 * a0.x + e1 * a1.x + e2 * a2.x + e3 * a3.x;
            acc.y += e0 * a0.y + e1 * a1.y + e2 * a2.y + e3 * a3.y;
            acc.z += e0 * b0.x + e1 * b1v.x + e2 * b2v.x + e3 * b3.x;
            acc.w += e0 * b0.y + e1 * b1v.y + e2 * b2v.y + e3 * b3.y;
        }
        for (; k < je; k++) {
            int s = __shfl_sync(FULL, sj, k);
            float e = leaky_exp(__ldg(&g_as1[s * 8 + head]) + adp);
            den += e;
            uint2 p = __ldg(&h16[s * 32 + l]);
            float2 a = __half22float2(*(__half2*)&p.x);
            float2 b = __half22float2(*(__half2*)&p.y);
            acc.x += e * a.x; acc.y += e * a.y;
            acc.z += e * b.x; acc.w += e * b.y;
        }
    }
    const float rinv = 1.f / (den + EPSV);
    float4 v = ((const float4*)b1)[l];
    v.x += acc.x * rinv; v.y += acc.y * rinv;
    v.z += acc.z * rinv; v.w += acc.w * rinv;
    v.x = v.x > 0.f ? v.x : __expf(v.x) - 1.f;
    v.y = v.y > 0.f ? v.y : __expf(v.y) - 1.f;
    v.z = v.z > 0.f ? v.z : __expf(v.z) - 1.f;
    v.w = v.w > 0.f ? v.w : __expf(v.w) - 1.f;
    *(uint2*)&g_out1h[n * 64 + 2 * l] = pack_half4(v);     // fp16 store
}

// ---------------- 3. GEMM2 (f32x2): g2(fp16) = elu_h(fp16) @ W2 + alphas ----
__global__ __launch_bounds__(256) void gemm2_kernel(
    const float* __restrict__ W2, const float* __restrict__ a_src,
    const float* __restrict__ a_dst)
{
    __shared__ float4 sW[128 * 10];
    __shared__ float4 sas[10], sad[10];
    __shared__ float  sx[256 * 17];
    const int tid = threadIdx.x;
    const int node = blockIdx.x * 256 + tid;
    const float4* W4 = (const float4*)W2;
    const ulonglong2* sW2p = (const ulonglong2*)sW;
    #pragma unroll
    for (int it = 0; it < 5; it++) sW[tid + it * 256] = W4[tid + it * 256];
    if (tid < 10) { sas[tid] = ((const float4*)a_src)[tid];
                    sad[tid] = ((const float4*)a_dst)[tid]; }
    const __half2* hin2 = g_out1h;

    unsigned long long acc2[10][2];
    #pragma unroll
    for (int j = 0; j < 10; j++) { acc2[j][0] = 0ull; acc2[j][1] = 0ull; }

    for (int kc = 0; kc < 8; kc++) {
        __syncthreads();
        #pragma unroll
        for (int it = 0; it < 8; it++) {             // 256 nodes x 8 half2
            int f = tid + it * 256;
            int nl2 = f >> 3, kp = f & 7;
            int gn = blockIdx.x * 256 + nl2;
            float2 fv = make_float2(0.f, 0.f);
            if (gn < NN) fv = __half22float2(hin2[(size_t)gn * 64 + kc * 8 + kp]);
            sx[nl2 * 17 + kp * 2 + 0] = fv.x;
            sx[nl2 * 17 + kp * 2 + 1] = fv.y;
        }
        __syncthreads();
        #pragma unroll
        for (int k = 0; k < 16; k++) {
            float xv = sx[tid * 17 + k];
            unsigned long long xd = pk2(xv, xv);
            const ulonglong2* wr = &sW2p[(kc * 16 + k) * 10];
            #pragma unroll
            for (int j = 0; j < 10; j++) {
                ulonglong2 w = wr[j];
                acc2[j][0] = fma2(xd, w.x, acc2[j][0]);
                acc2[j][1] = fma2(xd, w.y, acc2[j][1]);
            }
        }
    }
    if (node < NN) {
        float s = 0.f, d = 0.f;
        float4 accf[10];
        #pragma unroll
        for (int j = 0; j < 10; j++) {
            float2 lo = upk2(acc2[j][0]);
            float2 hi = upk2(acc2[j][1]);
            accf[j] = make_float4(lo.x, lo.y, hi.x, hi.y);
            s += dot4(accf[j], sas[j]);
            d += dot4(accf[j], sad[j]);
        }
        #pragma unroll
        for (int j = 0; j < 10; j++)
            *(uint2*)&g_g2h[node * 20 + 2 * j] = pack_half4(accf[j]);
        g_as2[node] = s;
        g_ad2[node] = d;
    }
}

// ---------------- 4. L2 fused aggregate: TWO nodes per warp -----------------
// 16-lane half per node; intra-loop shuffles use the HALF-LOCAL mask (the
// halves diverge in the k-loops, so a FULL mask there is illegal).
__global__ __launch_bounds__(256) void agg2_kernel(
    const float* __restrict__ b2, float* __restrict__ out)
{
    const int w = (blockIdx.x * 256 + threadIdx.x) >> 5;   // warp id
    const int l = threadIdx.x & 31;
    const int half = l >> 4, ll = l & 15;
    const unsigned HM = 0xFFFFu << (half * 16);            // half-local mask
    const int n = 2 * w + half;                            // NN even: exact
    const int beg = g_off[n], end = g_off[n + 1];
    const float ad2n = g_ad2[n];
    const bool act = ll < 10;
    const uint2* g24 = (const uint2*)g_g2h;      // [n*10 + c] -> 4 halves

    float den = 0.f;
    float4 acc = make_float4(0.f, 0.f, 0.f, 0.f);

    int nIter = (end - beg + 15) >> 4;
    int oIter = __shfl_xor_sync(FULL, nIter, 16);
    const int mIter = max(nIter, oIter);

    for (int it = 0; it < mIter; it++) {
        const int base = beg + it * 16;
        const int je = min(16, end - base);      // may be <= 0 for this half
        const int sj = (ll < je && je > 0) ? __ldg(&g_ssrc[base + ll]) : 0;
        int k = 0;
        #pragma unroll 1
        for (; k + 4 <= je; k += 4) {
            int s0 = __shfl_sync(HM, sj, k,     16);
            int s1 = __shfl_sync(HM, sj, k + 1, 16);
            int s2 = __shfl_sync(HM, sj, k + 2, 16);
            int s3 = __shfl_sync(HM, sj, k + 3, 16);
            float e0 = leaky_exp(__ldg(&g_as2[s0]) + ad2n);
            float e1 = leaky_exp(__ldg(&g_as2[s1]) + ad2n);
            float e2 = leaky_exp(__ldg(&g_as2[s2]) + ad2n);
            float e3 = leaky_exp(__ldg(&g_as2[s3]) + ad2n);
            den += (e0 + e1) + (e2 + e3);
            if (act) {
                uint2 p0 = __ldg(&g24[s0 * 10 + ll]);
                uint2 p1 = __ldg(&g24[s1 * 10 + ll]);
                uint2 p2 = __ldg(&g24[s2 * 10 + ll]);
                uint2 p3 = __ldg(&g24[s3 * 10 + ll]);
                float2 a0 = __half22float2(*(__half2*)&p0.x), b0 = __half22float2(*(__half2*)&p0.y);
                float2 a1 = __half22float2(*(__half2*)&p1.x), b1v = __half22float2(*(__half2*)&p1.y);
                float2 a2 = __half22float2(*(__half2*)&p2.x), b2v = __half22float2(*(__half2*)&p2.y);
                float2 a3 = __half22float2(*(__half2*)&p3.x), b3 = __half22float2(*(__half2*)&p3.y);
                acc.x += e0 * a0.x + e1 * a1.x + e2 * a2.x + e3 * a3.x;
                acc.y += e0 * a0.y + e1 * a1.y + e2 * a2.y + e3 * a3.y;
                acc.z += e0 * b0.x + e1 * b1v.x + e2 * b2v.x + e3 * b3.x;
                acc.w += e0 * b0.y + e1 * b1v.y + e2 * b2v.y + e3 * b3.y;
            }
        }
        #pragma unroll 1
        for (; k < je; k++) {
            int s = __shfl_sync(HM, sj, k, 16);
            float e = leaky_exp(__ldg(&g_as2[s]) + ad2n);
            den += e;
            if (act) {
                uint2 p = __ldg(&g24[s * 10 + ll]);
                float2 a = __half22float2(*(__half2*)&p.x);
                float2 b = __half22float2(*(__half2*)&p.y);
                acc.x += e * a.x; acc.y += e * a.y;
                acc.z += e * b.x; acc.w += e * b.y;
            }
        }
    }
    const float rinv = 1.f / (den + EPSV);

    float4 v = make_float4(-1e30f, -1e30f, -1e30f, -1e30f);
    if (act) {
        v = ((const float4*)b2)[ll];
        v.x += acc.x * rinv; v.y += acc.y * rinv;
        v.z += acc.z * rinv; v.w += acc.w * rinv;
    }
    // all 32 lanes execute these reductions -> FULL mask legal; xor offsets
    // < 16 keep values within each half.
    float mx = act ? fmaxf(fmaxf(v.x, v.y), fmaxf(v.z, v.w)) : -1e30f;
    #pragma unroll
    for (int o = 8; o; o >>= 1) mx = fmaxf(mx, __shfl_xor_sync(FULL, mx, o));
    float sm = 0.f;
    if (act) sm = __expf(v.x - mx) + __expf(v.y - mx) + __expf(v.z - mx) + __expf(v.w - mx);
    #pragma unroll
    for (int o = 8; o; o >>= 1) sm += __shfl_xor_sync(FULL, sm, o);
    float lse = mx + logf(sm);
    if (act)
        ((float4*)out)[n * 10 + ll] =
            make_float4(v.x - lse, v.y - lse, v.z - lse, v.w - lse);
}

// ---------------- launch ----------------
extern "C" void kernel_launch(void* const* d_in, const int* in_sizes, int n_in,
                              void* d_out, int out_size)
{
    const float* x      = (const float*)d_in[0];
    const int*   eidx   = (const int*)d_in[1];
    const float* W1     = (const float*)d_in[2];
    const float* a_src1 = (const float*)d_in[3];
    const float* a_dst1 = (const float*)d_in[4];
    const float* b1     = (const float*)d_in[5];
    const float* W2     = (const float*)d_in[6];
    const float* a_src2 = (const float*)d_in[7];
    const float* a_dst2 = (const float*)d_in[8];
    const float* b2     = (const float*)d_in[9];
    const int* src = eidx;
    const int* dst = eidx + EE;
    float* out = (float*)d_out;

    // Side stream + events for fork/join overlap of the CSR build with gemm1.
    static cudaStream_t sB = nullptr;
    static cudaEvent_t evFork = nullptr, evJoin = nullptr;
    if (sB == nullptr) {
        cudaStreamCreateWithFlags(&sB, cudaStreamNonBlocking);
        cudaEventCreateWithFlags(&evFork, cudaEventDisableTiming);
        cudaEventCreateWithFlags(&evJoin, cudaEventDisableTiming);
    }

    const int G1_SMEM = (64 * 128 + 64 * 128) * 4;   // 64 KB
    (void)cudaFuncSetAttribute(gemm1_kernel,
                               cudaFuncAttributeMaxDynamicSharedMemorySize, G1_SMEM);

    // fork: sort chain on sB runs concurrently with gemm1 on the main stream
    cudaEventRecord(evFork, 0);
    cudaStreamWaitEvent(sB, evFork, 0);

    gemm1_kernel<<<(NN + 63) / 64, 256, G1_SMEM>>>(x, W1, a_src1, a_dst1); // main
    zero_kernel<<<(NN + 255) / 256, 256, 0, sB>>>();
    hist_kernel<<<(EE / 4 + 255) / 256, 256, 0, sB>>>(dst);
    scan1_kernel<<<98, 1024, 0, sB>>>();
    scanB_kernel<<<98, 1024, 0, sB>>>();
    scatter_kernel<<<(EE / 4 + 255) / 256, 256, 0, sB>>>(src, dst);

    // join: agg1 needs both gemm1 outputs and the CSR
    cudaEventRecord(evJoin, sB);
    cudaStreamWaitEvent(0, evJoin, 0);

    agg1_kernel<<<NN / 8, 256>>>(b1);
    gemm2_kernel<<<(NN + 255) / 256, 256>>>(W2, a_src2, a_dst2);
    agg2_kernel<<<NN / 16, 256>>>(b2, out);
}

// round 14
// speedup vs baseline: 1.7351x; 1.0459x over previous
#include <cuda_runtime.h>
#include <cuda_fp16.h>
#include <math.h>

#define NN 100000
#define EE 1600000
#define EPSV 1e-16f
#define NEG_SLOPE 0.2f
#define FULL 0xffffffffu

// ---------------- scratch (device globals; allocation-free) ----------------
__device__ uint4   g_h1h[NN * 16];     // h1 [N,128] fp16       25.6 MB (16B-aligned)
__device__ float   g_as1[NN * 8];      // alpha_src1 [N,8]       3.2 MB
__device__ float   g_ad1[NN * 8];      // alpha_dst1 [N,8]       3.2 MB
__device__ uint4   g_out1h[NN * 16];   // elu(out1) [N,128] fp16 25.6 MB
__device__ __half2 g_g2h[NN * 20];     // g2 [N,40] fp16           8 MB
__device__ float   g_as2[NN];          // alpha_src2 [N]
__device__ float   g_ad2[NN];          // alpha_dst2 [N]
// CSR sort scratch (g_deg self-cleans: hist fills, scatter drains to 0)
__device__ int     g_deg[NN];
__device__ int     g_off[NN + 1];
__device__ int     g_ssrc[EE];         // src sorted by dst      6.4 MB
__device__ int     g_bsum[128];

// ---------------- helpers ----------------
__device__ __forceinline__ void fma4(float4& a, float s, float4 b) {
    a.x += s * b.x; a.y += s * b.y; a.z += s * b.z; a.w += s * b.w;
}
__device__ __forceinline__ float dot4(float4 a, float4 b) {
    return a.x * b.x + a.y * b.y + a.z * b.z + a.w * b.w;
}
__device__ __forceinline__ float leaky_exp(float e) {
    float t = e > 0.f ? e : NEG_SLOPE * e;
    return __expf(t);
}
__device__ __forceinline__ uint2 pack_half4(float4 v) {
    __half2 p0 = __floats2half2_rn(v.x, v.y);
    __half2 p1 = __floats2half2_rn(v.z, v.w);
    return make_uint2(*(unsigned*)&p0, *(unsigned*)&p1);
}
// ---- packed fp32x2 (Blackwell FFMA2) ----
__device__ __forceinline__ unsigned long long pk2(float lo, float hi) {
    unsigned long long r;
    asm("mov.b64 %0, {%1, %2};" : "=l"(r) : "f"(lo), "f"(hi));
    return r;
}
__device__ __forceinline__ unsigned long long fma2(
    unsigned long long a, unsigned long long b, unsigned long long c) {
    unsigned long long d;
    asm("fma.rn.f32x2 %0, %1, %2, %3;" : "=l"(d) : "l"(a), "l"(b), "l"(c));
    return d;
}
__device__ __forceinline__ float2 upk2(unsigned long long v) {
    float2 f;
    asm("mov.b64 {%0, %1}, %2;" : "=f"(f.x), "=f"(f.y) : "l"(v));
    return f;
}

// ---------------- S1. histogram of dst (4 edges/thread) ----------------
__global__ __launch_bounds__(256) void hist_kernel(const int* __restrict__ dst) {
    int i = blockIdx.x * 256 + threadIdx.x;
    if (i < EE / 4) {
        int4 d = __ldcs(&((const int4*)dst)[i]);
        atomicAdd(&g_deg[d.x], 1);
        atomicAdd(&g_deg[d.y], 1);
        atomicAdd(&g_deg[d.z], 1);
        atomicAdd(&g_deg[d.w], 1);
    }
}

// ---------------- S2a. block-level exclusive scan of degrees ----------------
__global__ __launch_bounds__(1024) void scan1_kernel() {
    int t = threadIdx.x;
    int i = blockIdx.x * 1024 + t;
    int v = (i < NN) ? g_deg[i] : 0;
    int lane = t & 31, w = t >> 5;
    int x = v;
    #pragma unroll
    for (int o = 1; o < 32; o <<= 1) {
        int y = __shfl_up_sync(FULL, x, o);
        if (lane >= o) x += y;
    }
    __shared__ int wt[32];
    if (lane == 31) wt[w] = x;
    __syncthreads();
    if (w == 0) {
        int z = wt[lane];
        #pragma unroll
        for (int o = 1; o < 32; o <<= 1) {
            int y = __shfl_up_sync(FULL, z, o);
            if (lane >= o) z += y;
        }
        wt[lane] = z;
    }
    __syncthreads();
    int pre = (w ? wt[w - 1] : 0);
    if (i < NN) g_off[i] = pre + x - v;      // block-local exclusive
    if (t == 1023) g_bsum[blockIdx.x] = wt[31];
}

// ---------------- S2b. add block prefix ----------------
__global__ __launch_bounds__(1024) void scanB_kernel() {
    __shared__ int s[128];
    __shared__ int blockpre;
    int t = threadIdx.x;
    if (t < 128) s[t] = (t < 98) ? g_bsum[t] : 0;
    __syncthreads();
    if (t == 0) {
        int run = 0;
        for (int b = 0; b < blockIdx.x; b++) run += s[b];
        blockpre = run;
    }
    __syncthreads();
    int i = blockIdx.x * 1024 + t;
    if (i < NN) g_off[i] += blockpre;
    if (i == 0) g_off[NN] = EE;
}

// ---------------- S3. scatter (4 edges/thread; drains g_deg to 0) -----------
__global__ __launch_bounds__(256) void scatter_kernel(
    const int* __restrict__ src, const int* __restrict__ dst)
{
    int i = blockIdx.x * 256 + threadIdx.x;
    if (i < EE / 4) {
        int4 d = __ldcs(&((const int4*)dst)[i]);
        int4 s = __ldcs(&((const int4*)src)[i]);
        int p0 = g_off[d.x] + atomicSub(&g_deg[d.x], 1) - 1;
        int p1 = g_off[d.y] + atomicSub(&g_deg[d.y], 1) - 1;
        int p2 = g_off[d.z] + atomicSub(&g_deg[d.z], 1) - 1;
        int p3 = g_off[d.w] + atomicSub(&g_deg[d.w], 1) - 1;
        __stcs(&g_ssrc[p0], s.x);
        __stcs(&g_ssrc[p1], s.y);
        __stcs(&g_ssrc[p2], s.z);
        __stcs(&g_ssrc[p3], s.w);
    }
}

// ---------------- 1. GEMM1 (register-tiled, f32x2): h1(fp16)=x@W1 -----------
__global__ __launch_bounds__(256) void gemm1_kernel(
    const float* __restrict__ x, const float* __restrict__ W1,
    const float* __restrict__ a_src, const float* __restrict__ a_dst)
{
    extern __shared__ float smem[];
    float4* sW4 = (float4*)smem;                 // [k*32 + c4] (64 k-rows)
    float4* sx4 = (float4*)(smem + 64 * 128);    // [n*32 + k4]
    const ulonglong2* sW2 = (const ulonglong2*)smem;
    const int tid = threadIdx.x;
    const int cx = tid & 31;      // col quad
    const int ny = tid >> 5;      // node group of 8
    const int nbase = blockIdx.x * 64;
    const float4* W4 = (const float4*)W1;
    const float4* x4 = (const float4*)x;

    #pragma unroll
    for (int it = 0; it < 8; it++) {             // x: 2048 f4
        int f = tid + it * 256;
        int gn = nbase + (f >> 5);
        sx4[f] = (gn < NN) ? x4[(size_t)gn * 32 + (f & 31)]
                           : make_float4(0.f, 0.f, 0.f, 0.f);
    }

    unsigned long long c2[8][2];
    #pragma unroll
    for (int i = 0; i < 8; i++) { c2[i][0] = 0ull; c2[i][1] = 0ull; }

    #pragma unroll
    for (int ch = 0; ch < 2; ch++) {
        if (ch) __syncthreads();                 // drain reads of prev sW
        #pragma unroll
        for (int it = 0; it < 8; it++) {         // W chunk: 2048 f4
            int f = tid + it * 256;
            sW4[f] = W4[(ch * 64 + (f >> 5)) * 32 + (f & 31)];
        }
        __syncthreads();
        #pragma unroll 4
        for (int k = 0; k < 64; k += 4) {
            ulonglong2 w0 = sW2[(k + 0) * 32 + cx];
            ulonglong2 w1 = sW2[(k + 1) * 32 + cx];
            ulonglong2 w2 = sW2[(k + 2) * 32 + cx];
            ulonglong2 w3 = sW2[(k + 3) * 32 + cx];
            #pragma unroll
            for (int i = 0; i < 8; i++) {
                float4 xv = sx4[(ny * 8 + i) * 32 + ((ch * 64 + k) >> 2)];
                unsigned long long d0 = pk2(xv.x, xv.x);
                unsigned long long d1 = pk2(xv.y, xv.y);
                unsigned long long d2 = pk2(xv.z, xv.z);
                unsigned long long d3 = pk2(xv.w, xv.w);
                c2[i][0] = fma2(d0, w0.x, c2[i][0]);
                c2[i][1] = fma2(d0, w0.y, c2[i][1]);
                c2[i][0] = fma2(d1, w1.x, c2[i][0]);
                c2[i][1] = fma2(d1, w1.y, c2[i][1]);
                c2[i][0] = fma2(d2, w2.x, c2[i][0]);
                c2[i][1] = fma2(d2, w2.y, c2[i][1]);
                c2[i][0] = fma2(d3, w3.x, c2[i][0]);
                c2[i][1] = fma2(d3, w3.y, c2[i][1]);
            }
        }
    }

    // epilogue: unpack, store h1 (fp16) + per-head alpha dots
    const int head = cx >> 2, cq = cx & 3;
    const float4 asv = ((const float4*)a_src)[head * 4 + cq];
    const float4 adv = ((const float4*)a_dst)[head * 4 + cq];
    #pragma unroll
    for (int i = 0; i < 8; i++) {
        int gn = nbase + ny * 8 + i;
        float2 lo = upk2(c2[i][0]);
        float2 hi = upk2(c2[i][1]);
        float4 ci = make_float4(lo.x, lo.y, hi.x, hi.y);
        float ps = dot4(ci, asv);
        float pd = dot4(ci, adv);
        ps += __shfl_xor_sync(FULL, ps, 1); ps += __shfl_xor_sync(FULL, ps, 2);
        pd += __shfl_xor_sync(FULL, pd, 1); pd += __shfl_xor_sync(FULL, pd, 2);
        if (gn < NN) {
            ((uint2*)g_h1h)[gn * 32 + cx] = pack_half4(ci);
            if (cq == 0) { g_as1[gn * 8 + head] = ps; g_ad1[gn * 8 + head] = pd; }
        }
    }
}

// ---------------- 2. L1 aggregate: warp/node, TWO EDGES per step ------------
// lanes 0-15 = even edges, 16-31 = odd edges; each lane owns 8 channels
// (one uint4 of fp16). Divergence-free: invalid edge -> e=0 select.
__global__ __launch_bounds__(256) void agg1_kernel(const float* __restrict__ b1)
{
    const int n = (blockIdx.x * 256 + threadIdx.x) >> 5;   // node (grid exact)
    const int l = threadIdx.x & 31;
    const int half = l >> 4;       // which edge of the pair
    const int ll = l & 15;         // channel-group lane (8 channels)
    const int headl = ll >> 1;     // head of channels ll*8..ll*8+7
    const int beg = g_off[n], end = g_off[n + 1];
    const float adp = g_ad1[n * 8 + headl];

    float den = 0.f;
    float a0=0.f,a1=0.f,a2=0.f,a3=0.f,a4=0.f,a5=0.f,a6=0.f,a7=0.f;

    for (int base = beg; base < end; base += 32) {
        const int je = min(32, end - base);
        const int sj = (l < je) ? __ldg(&g_ssrc[base + l]) : 0;
        const int nst = (je + 1) >> 1;
        int i = 0;
        #pragma unroll 1
        for (; i + 2 <= nst; i += 2) {
            int e0i = 2 * i + half, e1i = e0i + 2;
            int s0 = __shfl_sync(FULL, sj, e0i);
            int s1 = __shfl_sync(FULL, sj, e1i);
            float x0 = leaky_exp(__ldg(&g_as1[s0 * 8 + headl]) + adp);
            float x1 = leaky_exp(__ldg(&g_as1[s1 * 8 + headl]) + adp);
            x0 = (e0i < je) ? x0 : 0.f;
            x1 = (e1i < je) ? x1 : 0.f;
            uint4 p0 = __ldg(&g_h1h[s0 * 16 + ll]);
            uint4 p1 = __ldg(&g_h1h[s1 * 16 + ll]);
            den += x0 + x1;
            float2 q;
            q = __half22float2(*(__half2*)&p0.x); a0 += x0*q.x; a1 += x0*q.y;
            q = __half22float2(*(__half2*)&p0.y); a2 += x0*q.x; a3 += x0*q.y;
            q = __half22float2(*(__half2*)&p0.z); a4 += x0*q.x; a5 += x0*q.y;
            q = __half22float2(*(__half2*)&p0.w); a6 += x0*q.x; a7 += x0*q.y;
            q = __half22float2(*(__half2*)&p1.x); a0 += x1*q.x; a1 += x1*q.y;
            q = __half22float2(*(__half2*)&p1.y); a2 += x1*q.x; a3 += x1*q.y;
            q = __half22float2(*(__half2*)&p1.z); a4 += x1*q.x; a5 += x1*q.y;
            q = __half22float2(*(__half2*)&p1.w); a6 += x1*q.x; a7 += x1*q.y;
        }
        #pragma unroll 1
        for (; i < nst; i++) {
            int ei = 2 * i + half;
            int s = __shfl_sync(FULL, sj, ei);
            float e = leaky_exp(__ldg(&g_as1[s * 8 + headl]) + adp);
            e = (ei < je) ? e : 0.f;
            uint4 p = __ldg(&g_h1h[s * 16 + ll]);
            den += e;
            float2 q;
            q = __half22float2(*(__half2*)&p.x); a0 += e*q.x; a1 += e*q.y;
            q = __half22float2(*(__half2*)&p.y); a2 += e*q.x; a3 += e*q.y;
            q = __half22float2(*(__half2*)&p.z); a4 += e*q.x; a5 += e*q.y;
            q = __half22float2(*(__half2*)&p.w); a6 += e*q.x; a7 += e*q.y;
        }
    }
    // combine halves (all lanes converged)
    a0 += __shfl_xor_sync(FULL, a0, 16); a1 += __shfl_xor_sync(FULL, a1, 16);
    a2 += __shfl_xor_sync(FULL, a2, 16); a3 += __shfl_xor_sync(FULL, a3, 16);
    a4 += __shfl_xor_sync(FULL, a4, 16); a5 += __shfl_xor_sync(FULL, a5, 16);
    a6 += __shfl_xor_sync(FULL, a6, 16); a7 += __shfl_xor_sync(FULL, a7, 16);
    den += __shfl_xor_sync(FULL, den, 16);

    const float rinv = 1.f / (den + EPSV);
    const float4* b14 = (const float4*)b1;
    float4 bA = b14[ll * 2], bB = b14[ll * 2 + 1];
    float v0 = bA.x + a0 * rinv, v1 = bA.y + a1 * rinv;
    float v2 = bA.z + a2 * rinv, v3 = bA.w + a3 * rinv;
    float v4 = bB.x + a4 * rinv, v5 = bB.y + a5 * rinv;
    float v6 = bB.z + a6 * rinv, v7 = bB.w + a7 * rinv;
    v0 = v0 > 0.f ? v0 : __expf(v0) - 1.f;
    v1 = v1 > 0.f ? v1 : __expf(v1) - 1.f;
    v2 = v2 > 0.f ? v2 : __expf(v2) - 1.f;
    v3 = v3 > 0.f ? v3 : __expf(v3) - 1.f;
    v4 = v4 > 0.f ? v4 : __expf(v4) - 1.f;
    v5 = v5 > 0.f ? v5 : __expf(v5) - 1.f;
    v6 = v6 > 0.f ? v6 : __expf(v6) - 1.f;
    v7 = v7 > 0.f ? v7 : __expf(v7) - 1.f;
    if (half == 0) {
        uint4 o;
        __half2 t0 = __floats2half2_rn(v0, v1); o.x = *(unsigned*)&t0;
        __half2 t1 = __floats2half2_rn(v2, v3); o.y = *(unsigned*)&t1;
        __half2 t2 = __floats2half2_rn(v4, v5); o.z = *(unsigned*)&t2;
        __half2 t3 = __floats2half2_rn(v6, v7); o.w = *(unsigned*)&t3;
        g_out1h[n * 16 + ll] = o;
    }
}

// ---------------- 3. GEMM2 (f32x2): g2(fp16) = elu_h(fp16) @ W2 + alphas ----
__global__ __launch_bounds__(256) void gemm2_kernel(
    const float* __restrict__ W2, const float* __restrict__ a_src,
    const float* __restrict__ a_dst)
{
    __shared__ float4 sW[128 * 10];
    __shared__ float4 sas[10], sad[10];
    __shared__ float  sx[256 * 17];
    const int tid = threadIdx.x;
    const int node = blockIdx.x * 256 + tid;
    const float4* W4 = (const float4*)W2;
    const ulonglong2* sW2p = (const ulonglong2*)sW;
    #pragma unroll
    for (int it = 0; it < 5; it++) sW[tid + it * 256] = W4[tid + it * 256];
    if (tid < 10) { sas[tid] = ((const float4*)a_src)[tid];
                    sad[tid] = ((const float4*)a_dst)[tid]; }
    const __half2* hin2 = (const __half2*)g_out1h;

    unsigned long long acc2[10][2];
    #pragma unroll
    for (int j = 0; j < 10; j++) { acc2[j][0] = 0ull; acc2[j][1] = 0ull; }

    for (int kc = 0; kc < 8; kc++) {
        __syncthreads();
        #pragma unroll
        for (int it = 0; it < 8; it++) {             // 256 nodes x 8 half2
            int f = tid + it * 256;
            int nl2 = f >> 3, kp = f & 7;
            int gn = blockIdx.x * 256 + nl2;
            float2 fv = make_float2(0.f, 0.f);
            if (gn < NN) fv = __half22float2(hin2[(size_t)gn * 64 + kc * 8 + kp]);
            sx[nl2 * 17 + kp * 2 + 0] = fv.x;
            sx[nl2 * 17 + kp * 2 + 1] = fv.y;
        }
        __syncthreads();
        #pragma unroll
        for (int k = 0; k < 16; k++) {
            float xv = sx[tid * 17 + k];
            unsigned long long xd = pk2(xv, xv);
            const ulonglong2* wr = &sW2p[(kc * 16 + k) * 10];
            #pragma unroll
            for (int j = 0; j < 10; j++) {
                ulonglong2 w = wr[j];
                acc2[j][0] = fma2(xd, w.x, acc2[j][0]);
                acc2[j][1] = fma2(xd, w.y, acc2[j][1]);
            }
        }
    }
    if (node < NN) {
        float s = 0.f, d = 0.f;
        float4 accf[10];
        #pragma unroll
        for (int j = 0; j < 10; j++) {
            float2 lo = upk2(acc2[j][0]);
            float2 hi = upk2(acc2[j][1]);
            accf[j] = make_float4(lo.x, lo.y, hi.x, hi.y);
            s += dot4(accf[j], sas[j]);
            d += dot4(accf[j], sad[j]);
        }
        #pragma unroll
        for (int j = 0; j < 10; j++)
            *(uint2*)&g_g2h[node * 20 + 2 * j] = pack_half4(accf[j]);
        g_as2[node] = s;
        g_ad2[node] = d;
    }
}

// ---------------- 4. L2 fused aggregate: TWO nodes per warp -----------------
__global__ __launch_bounds__(256) void agg2_kernel(
    const float* __restrict__ b2, float* __restrict__ out)
{
    const int w = (blockIdx.x * 256 + threadIdx.x) >> 5;   // warp id
    const int l = threadIdx.x & 31;
    const int half = l >> 4, ll = l & 15;
    const unsigned HM = 0xFFFFu << (half * 16);            // half-local mask
    const int n = 2 * w + half;                            // NN even: exact
    const int beg = g_off[n], end = g_off[n + 1];
    const float ad2n = g_ad2[n];
    const bool act = ll < 10;
    const uint2* g24 = (const uint2*)g_g2h;      // [n*10 + c] -> 4 halves

    float den = 0.f;
    float4 acc = make_float4(0.f, 0.f, 0.f, 0.f);

    int nIter = (end - beg + 15) >> 4;
    int oIter = __shfl_xor_sync(FULL, nIter, 16);
    const int mIter = max(nIter, oIter);

    for (int it = 0; it < mIter; it++) {
        const int base = beg + it * 16;
        const int je = min(16, end - base);      // may be <= 0 for this half
        const int sj = (ll < je && je > 0) ? __ldg(&g_ssrc[base + ll]) : 0;
        int k = 0;
        #pragma unroll 1
        for (; k + 4 <= je; k += 4) {
            int s0 = __shfl_sync(HM, sj, k,     16);
            int s1 = __shfl_sync(HM, sj, k + 1, 16);
            int s2 = __shfl_sync(HM, sj, k + 2, 16);
            int s3 = __shfl_sync(HM, sj, k + 3, 16);
            float e0 = leaky_exp(__ldg(&g_as2[s0]) + ad2n);
            float e1 = leaky_exp(__ldg(&g_as2[s1]) + ad2n);
            float e2 = leaky_exp(__ldg(&g_as2[s2]) + ad2n);
            float e3 = leaky_exp(__ldg(&g_as2[s3]) + ad2n);
            den += (e0 + e1) + (e2 + e3);
            if (act) {
                uint2 p0 = __ldg(&g24[s0 * 10 + ll]);
                uint2 p1 = __ldg(&g24[s1 * 10 + ll]);
                uint2 p2 = __ldg(&g24[s2 * 10 + ll]);
                uint2 p3 = __ldg(&g24[s3 * 10 + ll]);
                float2 a0 = __half22float2(*(__half2*)&p0.x), b0 = __half22float2(*(__half2*)&p0.y);
                float2 a1 = __half22float2(*(__half2*)&p1.x), b1v = __half22float2(*(__half2*)&p1.y);
                float2 a2 = __half22float2(*(__half2*)&p2.x), b2v = __half22float2(*(__half2*)&p2.y);
                float2 a3 = __half22float2(*(__half2*)&p3.x), b3 = __half22float2(*(__half2*)&p3.y);
                acc.x += e0 * a0.x + e1 * a1.x + e2 * a2.x + e3 * a3.x;
                acc.y += e0 * a0.y + e1 * a1.y + e2 * a2.y + e3 * a3.y;
                acc.z += e0 * b0.x + e1 * b1v.x + e2 * b2v.x + e3 * b3.x;
                acc.w += e0 * b0.y + e1 * b1v.y + e2 * b2v.y + e3 * b3.y;
            }
        }
        #pragma unroll 1
        for (; k < je; k++) {
            int s = __shfl_sync(HM, sj, k, 16);
            float e = leaky_exp(__ldg(&g_as2[s]) + ad2n);
            den += e;
            if (act) {
                uint2 p = __ldg(&g24[s * 10 + ll]);
                float2 a = __half22float2(*(__half2*)&p.x);
                float2 b = __half22float2(*(__half2*)&p.y);
                acc.x += e * a.x; acc.y += e * a.y;
                acc.z += e * b.x; acc.w += e * b.y;
            }
        }
    }
    const float rinv = 1.f / (den + EPSV);

    float4 v = make_float4(-1e30f, -1e30f, -1e30f, -1e30f);
    if (act) {
        v = ((const float4*)b2)[ll];
        v.x += acc.x * rinv; v.y += acc.y * rinv;
        v.z += acc.z * rinv; v.w += acc.w * rinv;
    }
    float mx = act ? fmaxf(fmaxf(v.x, v.y), fmaxf(v.z, v.w)) : -1e30f;
    #pragma unroll
    for (int o = 8; o; o >>= 1) mx = fmaxf(mx, __shfl_xor_sync(FULL, mx, o));
    float sm = 0.f;
    if (act) sm = __expf(v.x - mx) + __expf(v.y - mx) + __expf(v.z - mx) + __expf(v.w - mx);
    #pragma unroll
    for (int o = 8; o; o >>= 1) sm += __shfl_xor_sync(FULL, sm, o);
    float lse = mx + logf(sm);
    if (act)
        ((float4*)out)[n * 10 + ll] =
            make_float4(v.x - lse, v.y - lse, v.z - lse, v.w - lse);
}

// ---------------- launch ----------------
extern "C" void kernel_launch(void* const* d_in, const int* in_sizes, int n_in,
                              void* d_out, int out_size)
{
    const float* x      = (const float*)d_in[0];
    const int*   eidx   = (const int*)d_in[1];
    const float* W1     = (const float*)d_in[2];
    const float* a_src1 = (const float*)d_in[3];
    const float* a_dst1 = (const float*)d_in[4];
    const float* b1     = (const float*)d_in[5];
    const float* W2     = (const float*)d_in[6];
    const float* a_src2 = (const float*)d_in[7];
    const float* a_dst2 = (const float*)d_in[8];
    const float* b2     = (const float*)d_in[9];
    const int* src = eidx;
    const int* dst = eidx + EE;
    float* out = (float*)d_out;

    // Side stream + events for fork/join overlap of the CSR build with gemm1.
    static cudaStream_t sB = nullptr;
    static cudaEvent_t evFork = nullptr, evJoin = nullptr;
    if (sB == nullptr) {
        cudaStreamCreateWithFlags(&sB, cudaStreamNonBlocking);
        cudaEventCreateWithFlags(&evFork, cudaEventDisableTiming);
        cudaEventCreateWithFlags(&evJoin, cudaEventDisableTiming);
    }

    const int G1_SMEM = (64 * 128 + 64 * 128) * 4;   // 64 KB
    (void)cudaFuncSetAttribute(gemm1_kernel,
                               cudaFuncAttributeMaxDynamicSharedMemorySize, G1_SMEM);

    // fork: sort chain on sB runs concurrently with gemm1 on the main stream
    cudaEventRecord(evFork, 0);
    cudaStreamWaitEvent(sB, evFork, 0);

    gemm1_kernel<<<(NN + 63) / 64, 256, G1_SMEM>>>(x, W1, a_src1, a_dst1); // main
    hist_kernel<<<(EE / 4 + 255) / 256, 256, 0, sB>>>(dst);
    scan1_kernel<<<98, 1024, 0, sB>>>();
    scanB_kernel<<<98, 1024, 0, sB>>>();
    scatter_kernel<<<(EE / 4 + 255) / 256, 256, 0, sB>>>(src, dst);

    // join: agg1 needs both gemm1 outputs and the CSR
    cudaEventRecord(evJoin, sB);
    cudaStreamWaitEvent(0, evJoin, 0);

    agg1_kernel<<<NN / 8, 256>>>(b1);
    gemm2_kernel<<<(NN + 255) / 256, 256>>>(W2, a_src2, a_dst2);
    agg2_kernel<<<NN / 16, 256>>>(b2, out);
}